// round 1
// baseline (speedup 1.0000x reference)
#include <cuda_runtime.h>
#include <math.h>

// Problem constants
constexpr int cB   = 2;
constexpr int cT   = 2048;
constexpr int cE   = 2048;
constexpr int cH   = 16;
constexpr int cKVH = 8;
constexpr int cD   = 128;

// Scratch (device globals; allocation-free rule)
__device__ float g_q [(size_t)cB * cH   * cT * cD];   // (b,h,t,d)
__device__ float g_k [(size_t)cB * cKVH * cT * cD];   // (b,kvh,t,d)
__device__ float g_v [(size_t)cB * cKVH * cT * cD];   // (b,kvh,t,d)
__device__ float g_ao[(size_t)cB * cT * cH * cD];     // (b,t,h,d) for out-proj

// ---------------------------------------------------------------------------
// Classic 128x128x16 SGEMM, 256 threads, 8x8 per thread.
// mode 0: C row-major [M,N].  mode 1: scatter to (b, h=col/128, t, d) layout.
// ---------------------------------------------------------------------------
__global__ __launch_bounds__(256) void sgemm_kernel(
    const float* __restrict__ A, const float* __restrict__ B,
    float* __restrict__ C, int N, int K, int mode, int HH)
{
    __shared__ float As[16 * 132];   // transposed: As[k][m]
    __shared__ float Bs[16 * 132];   // Bs[k][n]

    const int tid = threadIdx.x;
    const int rowBase = blockIdx.y * 128;
    const int colBase = blockIdx.x * 128;
    const int tr = tid >> 4;         // 0..15
    const int tc = tid & 15;         // 0..15

    const int aRow = tid >> 2;            // 0..63
    const int aCol = (tid & 3) << 2;      // 0,4,8,12
    const int bRow = tid >> 5;            // 0..7
    const int bCol = (tid & 31) << 2;     // 0..124

    float acc[8][8];
#pragma unroll
    for (int i = 0; i < 8; ++i)
#pragma unroll
        for (int j = 0; j < 8; ++j) acc[i][j] = 0.f;

    for (int kt = 0; kt < K; kt += 16) {
        __syncthreads();
#pragma unroll
        for (int off = 0; off < 128; off += 64) {
            float4 a = *(const float4*)(A + (size_t)(rowBase + aRow + off) * K + kt + aCol);
            As[(aCol + 0) * 132 + aRow + off] = a.x;
            As[(aCol + 1) * 132 + aRow + off] = a.y;
            As[(aCol + 2) * 132 + aRow + off] = a.z;
            As[(aCol + 3) * 132 + aRow + off] = a.w;
        }
#pragma unroll
        for (int off = 0; off < 16; off += 8) {
            *(float4*)(Bs + (bRow + off) * 132 + bCol) =
                *(const float4*)(B + (size_t)(kt + bRow + off) * N + colBase + bCol);
        }
        __syncthreads();

#pragma unroll
        for (int k = 0; k < 16; ++k) {
            float af[8], bf[8];
            *(float4*)(af)     = *(float4*)(As + k * 132 + tr * 8);
            *(float4*)(af + 4) = *(float4*)(As + k * 132 + tr * 8 + 4);
            *(float4*)(bf)     = *(float4*)(Bs + k * 132 + tc * 8);
            *(float4*)(bf + 4) = *(float4*)(Bs + k * 132 + tc * 8 + 4);
#pragma unroll
            for (int i = 0; i < 8; ++i)
#pragma unroll
                for (int j = 0; j < 8; ++j)
                    acc[i][j] = fmaf(af[i], bf[j], acc[i][j]);
        }
    }

#pragma unroll
    for (int i = 0; i < 8; ++i) {
        const int row = rowBase + tr * 8 + i;
        const int col = colBase + tc * 8;
        if (mode == 0) {
            *(float4*)(C + (size_t)row * N + col)     = *(float4*)&acc[i][0];
            *(float4*)(C + (size_t)row * N + col + 4) = *(float4*)&acc[i][4];
        } else {
            const int b = row >> 11;            // / cT
            const int t = row & (cT - 1);
            const int h = col >> 7;             // / cD
            const int d = col & (cD - 1);
            float* p = C + ((size_t)(b * HH + h) * cT + t) * cD + d;
            *(float4*)(p)     = *(float4*)&acc[i][0];
            *(float4*)(p + 4) = *(float4*)&acc[i][4];
        }
    }
}

// ---------------------------------------------------------------------------
// RoPE in-place on (b, nh, t, d) layout. One thread per (row, pair).
// ---------------------------------------------------------------------------
__global__ void rope_kernel(float* __restrict__ q, int total_pairs)
{
    int idx = blockIdx.x * blockDim.x + threadIdx.x;
    if (idx >= total_pairs) return;
    const int j   = idx & 63;
    const int row = idx >> 6;
    const int t   = row & (cT - 1);
    // inv_freq = 10000^(-2j/128) = 2^(-log2(10000) * j / 64)
    const float inv = exp2f(-13.287712379549449f * (float)j * (1.0f / 64.0f));
    const float f = (float)t * inv;
    float sn, cs;
    sincosf(f, &sn, &cs);
    float2 v = *(float2*)(q + (size_t)row * cD + j * 2);
    float2 r;
    r.x = v.x * cs - v.y * sn;
    r.y = v.x * sn + v.y * cs;
    *(float2*)(q + (size_t)row * cD + j * 2) = r;
}

// ---------------------------------------------------------------------------
// Flash attention fp32. One CTA per (b, h, qblock of 64 rows). 256 threads
// as 16x16. Q,K in smem transposed [d][row] (pad 68) for LDS.128; V row-major
// (pad 132); P via smem for the PV product. Online softmax.
// ---------------------------------------------------------------------------
__global__ __launch_bounds__(256) void attn_kernel(
    const float* __restrict__ Q, const float* __restrict__ K,
    const float* __restrict__ V, float* __restrict__ O)
{
    extern __shared__ float sm[];
    float* Qs = sm;                       // [128][68]
    float* Ks = sm + 128 * 68;            // [128][68]
    float* Vs = sm + 2 * 128 * 68;        // [64][132]
    float* Ps = Vs + 64 * 132;            // [64][68]

    const int bid = blockIdx.x;
    const int qb  = bid & 31;             // T/64 = 32 q-blocks
    const int h   = (bid >> 5) & 15;
    const int b   = bid >> 9;
    const int kvh = h >> 1;               // GQA: 2 q-heads per kv-head

    const float* qptr  = Q + ((size_t)(b * cH + h) * cT + qb * 64) * cD;
    const float* kbase = K + (size_t)(b * cKVH + kvh) * cT * cD;
    const float* vbase = V + (size_t)(b * cKVH + kvh) * cT * cD;

    const int tid = threadIdx.x;
    const int ty = tid >> 4;   // 0..15 -> 4 q-rows each
    const int tx = tid & 15;   // 0..15 -> 4 kv-cols (S) / 8 d-cols (O)

    // Load Q tile transposed
    for (int i = tid; i < 64 * 32; i += 256) {
        const int r = i >> 5, d4 = (i & 31) << 2;
        float4 v = *(const float4*)(qptr + r * cD + d4);
        Qs[(d4 + 0) * 68 + r] = v.x;
        Qs[(d4 + 1) * 68 + r] = v.y;
        Qs[(d4 + 2) * 68 + r] = v.z;
        Qs[(d4 + 3) * 68 + r] = v.w;
    }

    float m[4], l[4], o[4][8];
#pragma unroll
    for (int i = 0; i < 4; ++i) {
        m[i] = -1e30f; l[i] = 0.f;
#pragma unroll
        for (int c = 0; c < 8; ++c) o[i][c] = 0.f;
    }

    const float scale = 0.08838834764831845f;  // 1/sqrt(128)
    const int qrow0 = qb * 64;

    for (int kt = 0; kt <= qb; ++kt) {
        __syncthreads();   // previous PV done; Q store visible on first iter
        const float* kp = kbase + kt * 64 * cD;
        const float* vp = vbase + kt * 64 * cD;
        for (int i = tid; i < 64 * 32; i += 256) {
            const int r = i >> 5, d4 = (i & 31) << 2;
            float4 kv = *(const float4*)(kp + r * cD + d4);
            Ks[(d4 + 0) * 68 + r] = kv.x;
            Ks[(d4 + 1) * 68 + r] = kv.y;
            Ks[(d4 + 2) * 68 + r] = kv.z;
            Ks[(d4 + 3) * 68 + r] = kv.w;
            *(float4*)(Vs + r * 132 + d4) = *(const float4*)(vp + r * cD + d4);
        }
        __syncthreads();

        // S = Q K^T (64x64 tile), 4x4 per thread
        float s[4][4];
#pragma unroll
        for (int i = 0; i < 4; ++i)
#pragma unroll
            for (int j = 0; j < 4; ++j) s[i][j] = 0.f;

        for (int d = 0; d < 128; ++d) {
            float4 qv = *(float4*)(Qs + d * 68 + ty * 4);
            float4 kv = *(float4*)(Ks + d * 68 + tx * 4);
            const float qa[4] = {qv.x, qv.y, qv.z, qv.w};
            const float ka[4] = {kv.x, kv.y, kv.z, kv.w};
#pragma unroll
            for (int i = 0; i < 4; ++i)
#pragma unroll
                for (int j = 0; j < 4; ++j)
                    s[i][j] = fmaf(qa[i], ka[j], s[i][j]);
        }

        const bool diag = (kt == qb);
#pragma unroll
        for (int i = 0; i < 4; ++i) {
            const int qr = qrow0 + ty * 4 + i;
            float mx = -1e30f;
#pragma unroll
            for (int j = 0; j < 4; ++j) {
                float sv = s[i][j] * scale;
                if (diag && (kt * 64 + tx * 4 + j) > qr) sv = -1e30f;
                s[i][j] = sv;
                mx = fmaxf(mx, sv);
            }
#pragma unroll
            for (int off = 8; off; off >>= 1)
                mx = fmaxf(mx, __shfl_xor_sync(0xffffffffu, mx, off));
            const float mnew = fmaxf(m[i], mx);
            const float corr = __expf(m[i] - mnew);
            float ls = 0.f;
#pragma unroll
            for (int j = 0; j < 4; ++j) {
                const float p = __expf(s[i][j] - mnew);
                s[i][j] = p;
                ls += p;
            }
#pragma unroll
            for (int off = 8; off; off >>= 1)
                ls += __shfl_xor_sync(0xffffffffu, ls, off);
            l[i] = l[i] * corr + ls;
            m[i] = mnew;
#pragma unroll
            for (int c = 0; c < 8; ++c) o[i][c] *= corr;
            float4 pv = make_float4(s[i][0], s[i][1], s[i][2], s[i][3]);
            *(float4*)(Ps + (ty * 4 + i) * 68 + tx * 4) = pv;
        }
        __syncthreads();

        // O += P V : thread owns rows ty*4+i, cols tx*8..tx*8+7
#pragma unroll 4
        for (int j = 0; j < 64; ++j) {
            float4 v0 = *(float4*)(Vs + j * 132 + tx * 8);
            float4 v1 = *(float4*)(Vs + j * 132 + tx * 8 + 4);
#pragma unroll
            for (int i = 0; i < 4; ++i) {
                const float p = Ps[(ty * 4 + i) * 68 + j];
                o[i][0] = fmaf(p, v0.x, o[i][0]);
                o[i][1] = fmaf(p, v0.y, o[i][1]);
                o[i][2] = fmaf(p, v0.z, o[i][2]);
                o[i][3] = fmaf(p, v0.w, o[i][3]);
                o[i][4] = fmaf(p, v1.x, o[i][4]);
                o[i][5] = fmaf(p, v1.y, o[i][5]);
                o[i][6] = fmaf(p, v1.z, o[i][6]);
                o[i][7] = fmaf(p, v1.w, o[i][7]);
            }
        }
    }

    // Epilogue: write (b, t, h, d) layout for the output projection
#pragma unroll
    for (int i = 0; i < 4; ++i) {
        const float inv = 1.0f / l[i];
        const int qr = qrow0 + ty * 4 + i;
        float* op = O + ((size_t)(b * cT + qr) * cH + h) * cD + tx * 8;
        float4 r0 = make_float4(o[i][0] * inv, o[i][1] * inv, o[i][2] * inv, o[i][3] * inv);
        float4 r1 = make_float4(o[i][4] * inv, o[i][5] * inv, o[i][6] * inv, o[i][7] * inv);
        *(float4*)(op)     = r0;
        *(float4*)(op + 4) = r1;
    }
}

// ---------------------------------------------------------------------------
extern "C" void kernel_launch(void* const* d_in, const int* in_sizes, int n_in,
                              void* d_out, int out_size)
{
    const float* x  = (const float*)d_in[0];
    // d_in[1] = causal mask (int32) — causality is known statically, unused
    const float* wq = (const float*)d_in[2];
    const float* wk = (const float*)d_in[3];
    const float* wv = (const float*)d_in[4];
    const float* wo = (const float*)d_in[5];
    float* out = (float*)d_out;

    void *pq, *pk, *pv, *pao;
    cudaGetSymbolAddress(&pq, g_q);
    cudaGetSymbolAddress(&pk, g_k);
    cudaGetSymbolAddress(&pv, g_v);
    cudaGetSymbolAddress(&pao, g_ao);
    float* q  = (float*)pq;
    float* k  = (float*)pk;
    float* v  = (float*)pv;
    float* ao = (float*)pao;

    const int M = cB * cT;  // 4096

    // QKV projections (scatter epilogue to (b,h,t,d))
    sgemm_kernel<<<dim3(cH * cD / 128, M / 128), 256>>>(x, wq, q, cH * cD, cE, 1, cH);
    sgemm_kernel<<<dim3(cKVH * cD / 128, M / 128), 256>>>(x, wk, k, cKVH * cD, cE, 1, cKVH);
    sgemm_kernel<<<dim3(cKVH * cD / 128, M / 128), 256>>>(x, wv, v, cKVH * cD, cE, 1, cKVH);

    // RoPE on q, k
    {
        int tp_q = cB * cH * cT * (cD / 2);
        int tp_k = cB * cKVH * cT * (cD / 2);
        rope_kernel<<<(tp_q + 255) / 256, 256>>>(q, tp_q);
        rope_kernel<<<(tp_k + 255) / 256, 256>>>(k, tp_k);
    }

    // Flash attention
    const int smem_bytes = (2 * 128 * 68 + 64 * 132 + 64 * 68) * 4;  // 120832
    cudaFuncSetAttribute(attn_kernel, cudaFuncAttributeMaxDynamicSharedMemorySize, smem_bytes);
    attn_kernel<<<cB * cH * (cT / 64), 256, smem_bytes>>>(q, k, v, ao);

    // Output projection (plain row-major epilogue)
    sgemm_kernel<<<dim3(cE / 128, M / 128), 256>>>(ao, wo, out, cE, cE, 0, 0);
}

// round 2
// speedup vs baseline: 1.4211x; 1.4211x over previous
#include <cuda_runtime.h>
#include <math.h>

// Problem constants
constexpr int cB   = 2;
constexpr int cT   = 2048;
constexpr int cE   = 2048;
constexpr int cH   = 16;
constexpr int cKVH = 8;
constexpr int cD   = 128;

// Scratch (device globals; allocation-free rule)
__device__ float g_q [(size_t)cB * cH   * cT * cD];   // (b,h,t,d)
__device__ float g_k [(size_t)cB * cKVH * cT * cD];   // (b,kvh,t,d)
__device__ float g_v [(size_t)cB * cKVH * cT * cD];   // (b,kvh,t,d)
__device__ float g_ao[(size_t)cB * cT * cH * cD];     // (b,t,h,d) for out-proj

__device__ __forceinline__ unsigned f2tf32(float f) {
    unsigned u;
    asm("cvt.rna.tf32.f32 %0, %1;" : "=r"(u) : "f"(f));
    return u;
}

// ---------------------------------------------------------------------------
// TF32 tensor-core GEMM. C[M,N] = A[M,K] * B[K,N], all fp32 in gmem.
// CTA tile 128x128x32, 256 threads = 8 warps (2 m x 4 n), warp tile 64x32,
// mma.sync m16n8k8 tf32. Register-double-buffered gmem prefetch.
// mode 0: C row-major.  mode 1: scatter to (b, h=col/128, t, d) layout.
// ---------------------------------------------------------------------------
__global__ __launch_bounds__(256) void tf32_gemm_kernel(
    const float* __restrict__ A, const float* __restrict__ B,
    float* __restrict__ C, int N, int K, int mode, int HH)
{
    __shared__ unsigned As[128][36];   // [m][k], pad 36: conflict-free frag loads
    __shared__ unsigned Bs[32][132];   // [k][n], pad 132

    const int tid  = threadIdx.x;
    const int lane = tid & 31;
    const int w    = tid >> 5;
    const int wm   = (w >> 2) * 64;    // warp m-offset (0 or 64)
    const int wn   = (w & 3) * 32;     // warp n-offset (0,32,64,96)
    const int gr   = lane >> 2;        // group row 0..7
    const int gc   = lane & 3;         // group col 0..3

    const int rowBase = blockIdx.y * 128;
    const int colBase = blockIdx.x * 128;

    // Global-load assignments
    const int aRow = tid >> 1;                 // 0..127
    const int aCol = (tid & 1) * 16;           // 0 or 16 (then +0,4,8,12)
    const int bRow = tid >> 3;                 // 0..31
    const int bCol = (tid & 7) * 16;           // 0..112 (then +0,4,8,12)

    const float* aPtr = A + (size_t)(rowBase + aRow) * K + aCol;
    const float* bPtr = B + (size_t)bRow * N + colBase + bCol;

    float acc[4][4][4];
#pragma unroll
    for (int mi = 0; mi < 4; ++mi)
#pragma unroll
        for (int ni = 0; ni < 4; ++ni)
#pragma unroll
            for (int c = 0; c < 4; ++c) acc[mi][ni][c] = 0.f;

    // Initial tile -> smem
#pragma unroll
    for (int j = 0; j < 4; ++j) {
        float4 a = *(const float4*)(aPtr + j * 4);
        As[aRow][aCol + j*4 + 0] = f2tf32(a.x);
        As[aRow][aCol + j*4 + 1] = f2tf32(a.y);
        As[aRow][aCol + j*4 + 2] = f2tf32(a.z);
        As[aRow][aCol + j*4 + 3] = f2tf32(a.w);
        float4 b = *(const float4*)(bPtr + j * 4);
        Bs[bRow][bCol + j*4 + 0] = f2tf32(b.x);
        Bs[bRow][bCol + j*4 + 1] = f2tf32(b.y);
        Bs[bRow][bCol + j*4 + 2] = f2tf32(b.z);
        Bs[bRow][bCol + j*4 + 3] = f2tf32(b.w);
    }
    __syncthreads();

    for (int kt = 0; kt < K; kt += 32) {
        const bool hasNext = (kt + 32) < K;
        float4 pa[4], pb[4];
        if (hasNext) {
#pragma unroll
            for (int j = 0; j < 4; ++j) {
                pa[j] = *(const float4*)(aPtr + (kt + 32) + j * 4);
                pb[j] = *(const float4*)(bPtr + (size_t)(kt + 32) * N + j * 4);
            }
        }

        // Compute 4 k-steps of 8
#pragma unroll
        for (int kk = 0; kk < 32; kk += 8) {
            unsigned af[4][4], bf[4][2];
#pragma unroll
            for (int mi = 0; mi < 4; ++mi) {
                const int r = wm + mi * 16 + gr;
                af[mi][0] = As[r    ][kk + gc    ];
                af[mi][1] = As[r + 8][kk + gc    ];
                af[mi][2] = As[r    ][kk + gc + 4];
                af[mi][3] = As[r + 8][kk + gc + 4];
            }
#pragma unroll
            for (int ni = 0; ni < 4; ++ni) {
                const int cN = wn + ni * 8 + gr;
                bf[ni][0] = Bs[kk + gc    ][cN];
                bf[ni][1] = Bs[kk + gc + 4][cN];
            }
#pragma unroll
            for (int mi = 0; mi < 4; ++mi)
#pragma unroll
                for (int ni = 0; ni < 4; ++ni) {
                    asm volatile(
                        "mma.sync.aligned.m16n8k8.row.col.f32.tf32.tf32.f32 "
                        "{%0,%1,%2,%3}, {%4,%5,%6,%7}, {%8,%9}, {%0,%1,%2,%3};"
                        : "+f"(acc[mi][ni][0]), "+f"(acc[mi][ni][1]),
                          "+f"(acc[mi][ni][2]), "+f"(acc[mi][ni][3])
                        : "r"(af[mi][0]), "r"(af[mi][1]),
                          "r"(af[mi][2]), "r"(af[mi][3]),
                          "r"(bf[ni][0]), "r"(bf[ni][1]));
                }
        }
        __syncthreads();
        if (hasNext) {
#pragma unroll
            for (int j = 0; j < 4; ++j) {
                As[aRow][aCol + j*4 + 0] = f2tf32(pa[j].x);
                As[aRow][aCol + j*4 + 1] = f2tf32(pa[j].y);
                As[aRow][aCol + j*4 + 2] = f2tf32(pa[j].z);
                As[aRow][aCol + j*4 + 3] = f2tf32(pa[j].w);
                Bs[bRow][bCol + j*4 + 0] = f2tf32(pb[j].x);
                Bs[bRow][bCol + j*4 + 1] = f2tf32(pb[j].y);
                Bs[bRow][bCol + j*4 + 2] = f2tf32(pb[j].z);
                Bs[bRow][bCol + j*4 + 3] = f2tf32(pb[j].w);
            }
            __syncthreads();
        }
    }

    // Epilogue. c0,c1 contiguous cols -> float2 stores.
#pragma unroll
    for (int mi = 0; mi < 4; ++mi) {
#pragma unroll
        for (int ni = 0; ni < 4; ++ni) {
            const int row0 = rowBase + wm + mi * 16 + gr;
            const int col  = colBase + wn + ni * 8 + gc * 2;
            if (mode == 0) {
                *(float2*)(C + (size_t)row0 * N + col) =
                    make_float2(acc[mi][ni][0], acc[mi][ni][1]);
                *(float2*)(C + (size_t)(row0 + 8) * N + col) =
                    make_float2(acc[mi][ni][2], acc[mi][ni][3]);
            } else {
                const int h = col >> 7;
                const int d = col & (cD - 1);
#pragma unroll
                for (int rr = 0; rr < 2; ++rr) {
                    const int row = row0 + rr * 8;
                    const int b = row >> 11;
                    const int t = row & (cT - 1);
                    float* p = C + ((size_t)(b * HH + h) * cT + t) * cD + d;
                    *(float2*)p = make_float2(acc[mi][ni][rr*2], acc[mi][ni][rr*2+1]);
                }
            }
        }
    }
}

// ---------------------------------------------------------------------------
// RoPE in-place on (b, nh, t, d) layout. One thread per (row, pair).
// ---------------------------------------------------------------------------
__global__ void rope_kernel(float* __restrict__ q, int total_pairs)
{
    int idx = blockIdx.x * blockDim.x + threadIdx.x;
    if (idx >= total_pairs) return;
    const int j   = idx & 63;
    const int row = idx >> 6;
    const int t   = row & (cT - 1);
    const float inv = exp2f(-13.287712379549449f * (float)j * (1.0f / 64.0f));
    const float f = (float)t * inv;
    float sn, cs;
    sincosf(f, &sn, &cs);
    float2 v = *(float2*)(q + (size_t)row * cD + j * 2);
    float2 r;
    r.x = v.x * cs - v.y * sn;
    r.y = v.x * sn + v.y * cs;
    *(float2*)(q + (size_t)row * cD + j * 2) = r;
}

// ---------------------------------------------------------------------------
// Flash attention fp32 (unchanged from R1 — passing, ~exact).
// ---------------------------------------------------------------------------
__global__ __launch_bounds__(256) void attn_kernel(
    const float* __restrict__ Q, const float* __restrict__ K,
    const float* __restrict__ V, float* __restrict__ O)
{
    extern __shared__ float sm[];
    float* Qs = sm;                       // [128][68]
    float* Ks = sm + 128 * 68;            // [128][68]
    float* Vs = sm + 2 * 128 * 68;        // [64][132]
    float* Ps = Vs + 64 * 132;            // [64][68]

    const int bid = blockIdx.x;
    const int qb  = bid & 31;
    const int h   = (bid >> 5) & 15;
    const int b   = bid >> 9;
    const int kvh = h >> 1;

    const float* qptr  = Q + ((size_t)(b * cH + h) * cT + qb * 64) * cD;
    const float* kbase = K + (size_t)(b * cKVH + kvh) * cT * cD;
    const float* vbase = V + (size_t)(b * cKVH + kvh) * cT * cD;

    const int tid = threadIdx.x;
    const int ty = tid >> 4;
    const int tx = tid & 15;

    for (int i = tid; i < 64 * 32; i += 256) {
        const int r = i >> 5, d4 = (i & 31) << 2;
        float4 v = *(const float4*)(qptr + r * cD + d4);
        Qs[(d4 + 0) * 68 + r] = v.x;
        Qs[(d4 + 1) * 68 + r] = v.y;
        Qs[(d4 + 2) * 68 + r] = v.z;
        Qs[(d4 + 3) * 68 + r] = v.w;
    }

    float m[4], l[4], o[4][8];
#pragma unroll
    for (int i = 0; i < 4; ++i) {
        m[i] = -1e30f; l[i] = 0.f;
#pragma unroll
        for (int c = 0; c < 8; ++c) o[i][c] = 0.f;
    }

    const float scale = 0.08838834764831845f;
    const int qrow0 = qb * 64;

    for (int kt = 0; kt <= qb; ++kt) {
        __syncthreads();
        const float* kp = kbase + kt * 64 * cD;
        const float* vp = vbase + kt * 64 * cD;
        for (int i = tid; i < 64 * 32; i += 256) {
            const int r = i >> 5, d4 = (i & 31) << 2;
            float4 kv = *(const float4*)(kp + r * cD + d4);
            Ks[(d4 + 0) * 68 + r] = kv.x;
            Ks[(d4 + 1) * 68 + r] = kv.y;
            Ks[(d4 + 2) * 68 + r] = kv.z;
            Ks[(d4 + 3) * 68 + r] = kv.w;
            *(float4*)(Vs + r * 132 + d4) = *(const float4*)(vp + r * cD + d4);
        }
        __syncthreads();

        float s[4][4];
#pragma unroll
        for (int i = 0; i < 4; ++i)
#pragma unroll
            for (int j = 0; j < 4; ++j) s[i][j] = 0.f;

        for (int d = 0; d < 128; ++d) {
            float4 qv = *(float4*)(Qs + d * 68 + ty * 4);
            float4 kv = *(float4*)(Ks + d * 68 + tx * 4);
            const float qa[4] = {qv.x, qv.y, qv.z, qv.w};
            const float ka[4] = {kv.x, kv.y, kv.z, kv.w};
#pragma unroll
            for (int i = 0; i < 4; ++i)
#pragma unroll
                for (int j = 0; j < 4; ++j)
                    s[i][j] = fmaf(qa[i], ka[j], s[i][j]);
        }

        const bool diag = (kt == qb);
#pragma unroll
        for (int i = 0; i < 4; ++i) {
            const int qr = qrow0 + ty * 4 + i;
            float mx = -1e30f;
#pragma unroll
            for (int j = 0; j < 4; ++j) {
                float sv = s[i][j] * scale;
                if (diag && (kt * 64 + tx * 4 + j) > qr) sv = -1e30f;
                s[i][j] = sv;
                mx = fmaxf(mx, sv);
            }
#pragma unroll
            for (int off = 8; off; off >>= 1)
                mx = fmaxf(mx, __shfl_xor_sync(0xffffffffu, mx, off));
            const float mnew = fmaxf(m[i], mx);
            const float corr = __expf(m[i] - mnew);
            float ls = 0.f;
#pragma unroll
            for (int j = 0; j < 4; ++j) {
                const float p = __expf(s[i][j] - mnew);
                s[i][j] = p;
                ls += p;
            }
#pragma unroll
            for (int off = 8; off; off >>= 1)
                ls += __shfl_xor_sync(0xffffffffu, ls, off);
            l[i] = l[i] * corr + ls;
            m[i] = mnew;
#pragma unroll
            for (int c = 0; c < 8; ++c) o[i][c] *= corr;
            float4 pv = make_float4(s[i][0], s[i][1], s[i][2], s[i][3]);
            *(float4*)(Ps + (ty * 4 + i) * 68 + tx * 4) = pv;
        }
        __syncthreads();

#pragma unroll 4
        for (int j = 0; j < 64; ++j) {
            float4 v0 = *(float4*)(Vs + j * 132 + tx * 8);
            float4 v1 = *(float4*)(Vs + j * 132 + tx * 8 + 4);
#pragma unroll
            for (int i = 0; i < 4; ++i) {
                const float p = Ps[(ty * 4 + i) * 68 + j];
                o[i][0] = fmaf(p, v0.x, o[i][0]);
                o[i][1] = fmaf(p, v0.y, o[i][1]);
                o[i][2] = fmaf(p, v0.z, o[i][2]);
                o[i][3] = fmaf(p, v0.w, o[i][3]);
                o[i][4] = fmaf(p, v1.x, o[i][4]);
                o[i][5] = fmaf(p, v1.y, o[i][5]);
                o[i][6] = fmaf(p, v1.z, o[i][6]);
                o[i][7] = fmaf(p, v1.w, o[i][7]);
            }
        }
    }

#pragma unroll
    for (int i = 0; i < 4; ++i) {
        const float inv = 1.0f / l[i];
        const int qr = qrow0 + ty * 4 + i;
        float* op = O + ((size_t)(b * cT + qr) * cH + h) * cD + tx * 8;
        float4 r0 = make_float4(o[i][0] * inv, o[i][1] * inv, o[i][2] * inv, o[i][3] * inv);
        float4 r1 = make_float4(o[i][4] * inv, o[i][5] * inv, o[i][6] * inv, o[i][7] * inv);
        *(float4*)(op)     = r0;
        *(float4*)(op + 4) = r1;
    }
}

// ---------------------------------------------------------------------------
extern "C" void kernel_launch(void* const* d_in, const int* in_sizes, int n_in,
                              void* d_out, int out_size)
{
    const float* x  = (const float*)d_in[0];
    const float* wq = (const float*)d_in[2];
    const float* wk = (const float*)d_in[3];
    const float* wv = (const float*)d_in[4];
    const float* wo = (const float*)d_in[5];
    float* out = (float*)d_out;

    void *pq, *pk, *pv, *pao;
    cudaGetSymbolAddress(&pq, g_q);
    cudaGetSymbolAddress(&pk, g_k);
    cudaGetSymbolAddress(&pv, g_v);
    cudaGetSymbolAddress(&pao, g_ao);
    float* q  = (float*)pq;
    float* k  = (float*)pk;
    float* v  = (float*)pv;
    float* ao = (float*)pao;

    const int M = cB * cT;  // 4096

    // QKV projections (TF32 tensor cores; scatter epilogue to (b,h,t,d))
    tf32_gemm_kernel<<<dim3(cH * cD / 128, M / 128), 256>>>(x, wq, q, cH * cD, cE, 1, cH);
    tf32_gemm_kernel<<<dim3(cKVH * cD / 128, M / 128), 256>>>(x, wk, k, cKVH * cD, cE, 1, cKVH);
    tf32_gemm_kernel<<<dim3(cKVH * cD / 128, M / 128), 256>>>(x, wv, v, cKVH * cD, cE, 1, cKVH);

    // RoPE on q, k
    {
        int tp_q = cB * cH * cT * (cD / 2);
        int tp_k = cB * cKVH * cT * (cD / 2);
        rope_kernel<<<(tp_q + 255) / 256, 256>>>(q, tp_q);
        rope_kernel<<<(tp_k + 255) / 256, 256>>>(k, tp_k);
    }

    // Flash attention (fp32)
    const int smem_bytes = (2 * 128 * 68 + 64 * 132 + 64 * 68) * 4;  // 120832
    cudaFuncSetAttribute(attn_kernel, cudaFuncAttributeMaxDynamicSharedMemorySize, smem_bytes);
    attn_kernel<<<cB * cH * (cT / 64), 256, smem_bytes>>>(q, k, v, ao);

    // Output projection (TF32 tensor cores, row-major epilogue)
    tf32_gemm_kernel<<<dim3(cE / 128, M / 128), 256>>>(ao, wo, out, cE, cE, 0, 0);
}

// round 6
// speedup vs baseline: 2.5025x; 1.7610x over previous
#include <cuda_runtime.h>
#include <math.h>

constexpr int cB   = 2;
constexpr int cT   = 2048;
constexpr int cE   = 2048;
constexpr int cH   = 16;
constexpr int cKVH = 8;
constexpr int cD   = 128;

__device__ float g_q [(size_t)cB * cH   * cT * cD];   // (b,h,t,d)
__device__ float g_k [(size_t)cB * cKVH * cT * cD];   // (b,kvh,t,d)
__device__ float g_vt[(size_t)cB * cKVH * cD * cT];   // (b,kvh,d,t)  V transposed
__device__ float g_ao[(size_t)cB * cT * cH * cD];     // (b,t,h,d)

__device__ __forceinline__ unsigned f2tf32(float f) {
    unsigned u;
    asm("cvt.rna.tf32.f32 %0, %1;" : "=r"(u) : "f"(f));
    return u;
}

// ---------------------------------------------------------------------------
// TF32 tensor-core GEMM. 128x128x32 tile, 256 thr, warp 64x32, m16n8k8.
// mode 0: C row-major. mode 1: scatter (b,h,t,d). mode 2: scatter (b,h,d,t).
// ---------------------------------------------------------------------------
__global__ __launch_bounds__(256) void tf32_gemm_kernel(
    const float* __restrict__ A, const float* __restrict__ B,
    float* __restrict__ C, int N, int K, int mode, int HH)
{
    __shared__ unsigned As[128][36];
    __shared__ unsigned Bs[32][132];

    const int tid  = threadIdx.x;
    const int lane = tid & 31;
    const int w    = tid >> 5;
    const int wm   = (w >> 2) * 64;
    const int wn   = (w & 3) * 32;
    const int gr   = lane >> 2;
    const int gc   = lane & 3;

    const int rowBase = blockIdx.y * 128;
    const int colBase = blockIdx.x * 128;

    const int aRow = tid >> 1;
    const int aCol = (tid & 1) * 16;
    const int bRow = tid >> 3;
    const int bCol = (tid & 7) * 16;

    const float* aPtr = A + (size_t)(rowBase + aRow) * K + aCol;
    const float* bPtr = B + (size_t)bRow * N + colBase + bCol;

    float acc[4][4][4];
#pragma unroll
    for (int mi = 0; mi < 4; ++mi)
#pragma unroll
        for (int ni = 0; ni < 4; ++ni)
#pragma unroll
            for (int c = 0; c < 4; ++c) acc[mi][ni][c] = 0.f;

#pragma unroll
    for (int j = 0; j < 4; ++j) {
        float4 a = *(const float4*)(aPtr + j * 4);
        As[aRow][aCol + j*4 + 0] = f2tf32(a.x);
        As[aRow][aCol + j*4 + 1] = f2tf32(a.y);
        As[aRow][aCol + j*4 + 2] = f2tf32(a.z);
        As[aRow][aCol + j*4 + 3] = f2tf32(a.w);
        float4 b = *(const float4*)(bPtr + j * 4);
        Bs[bRow][bCol + j*4 + 0] = f2tf32(b.x);
        Bs[bRow][bCol + j*4 + 1] = f2tf32(b.y);
        Bs[bRow][bCol + j*4 + 2] = f2tf32(b.z);
        Bs[bRow][bCol + j*4 + 3] = f2tf32(b.w);
    }
    __syncthreads();

    for (int kt = 0; kt < K; kt += 32) {
        const bool hasNext = (kt + 32) < K;
        float4 pa[4], pb[4];
        if (hasNext) {
#pragma unroll
            for (int j = 0; j < 4; ++j) {
                pa[j] = *(const float4*)(aPtr + (kt + 32) + j * 4);
                pb[j] = *(const float4*)(bPtr + (size_t)(kt + 32) * N + j * 4);
            }
        }

#pragma unroll
        for (int kk = 0; kk < 32; kk += 8) {
            unsigned af[4][4], bf[4][2];
#pragma unroll
            for (int mi = 0; mi < 4; ++mi) {
                const int r = wm + mi * 16 + gr;
                af[mi][0] = As[r    ][kk + gc    ];
                af[mi][1] = As[r + 8][kk + gc    ];
                af[mi][2] = As[r    ][kk + gc + 4];
                af[mi][3] = As[r + 8][kk + gc + 4];
            }
#pragma unroll
            for (int ni = 0; ni < 4; ++ni) {
                const int cN = wn + ni * 8 + gr;
                bf[ni][0] = Bs[kk + gc    ][cN];
                bf[ni][1] = Bs[kk + gc + 4][cN];
            }
#pragma unroll
            for (int mi = 0; mi < 4; ++mi)
#pragma unroll
                for (int ni = 0; ni < 4; ++ni) {
                    asm volatile(
                        "mma.sync.aligned.m16n8k8.row.col.f32.tf32.tf32.f32 "
                        "{%0,%1,%2,%3}, {%4,%5,%6,%7}, {%8,%9}, {%0,%1,%2,%3};"
                        : "+f"(acc[mi][ni][0]), "+f"(acc[mi][ni][1]),
                          "+f"(acc[mi][ni][2]), "+f"(acc[mi][ni][3])
                        : "r"(af[mi][0]), "r"(af[mi][1]),
                          "r"(af[mi][2]), "r"(af[mi][3]),
                          "r"(bf[ni][0]), "r"(bf[ni][1]));
                }
        }
        __syncthreads();
        if (hasNext) {
#pragma unroll
            for (int j = 0; j < 4; ++j) {
                As[aRow][aCol + j*4 + 0] = f2tf32(pa[j].x);
                As[aRow][aCol + j*4 + 1] = f2tf32(pa[j].y);
                As[aRow][aCol + j*4 + 2] = f2tf32(pa[j].z);
                As[aRow][aCol + j*4 + 3] = f2tf32(pa[j].w);
                Bs[bRow][bCol + j*4 + 0] = f2tf32(pb[j].x);
                Bs[bRow][bCol + j*4 + 1] = f2tf32(pb[j].y);
                Bs[bRow][bCol + j*4 + 2] = f2tf32(pb[j].z);
                Bs[bRow][bCol + j*4 + 3] = f2tf32(pb[j].w);
            }
            __syncthreads();
        }
    }

#pragma unroll
    for (int mi = 0; mi < 4; ++mi) {
#pragma unroll
        for (int ni = 0; ni < 4; ++ni) {
            const int row0 = rowBase + wm + mi * 16 + gr;
            const int col  = colBase + wn + ni * 8 + gc * 2;
            if (mode == 0) {
                *(float2*)(C + (size_t)row0 * N + col) =
                    make_float2(acc[mi][ni][0], acc[mi][ni][1]);
                *(float2*)(C + (size_t)(row0 + 8) * N + col) =
                    make_float2(acc[mi][ni][2], acc[mi][ni][3]);
            } else if (mode == 1) {
                const int h = col >> 7;
                const int d = col & (cD - 1);
#pragma unroll
                for (int rr = 0; rr < 2; ++rr) {
                    const int row = row0 + rr * 8;
                    const int b = row >> 11;
                    const int t = row & (cT - 1);
                    float* p = C + ((size_t)(b * HH + h) * cT + t) * cD + d;
                    *(float2*)p = make_float2(acc[mi][ni][rr*2], acc[mi][ni][rr*2+1]);
                }
            } else {  // mode 2: (b, h, d, t) transposed scatter
                const int h = col >> 7;
                const int d = col & (cD - 1);
#pragma unroll
                for (int rr = 0; rr < 2; ++rr) {
                    const int row = row0 + rr * 8;
                    const int b = row >> 11;
                    const int t = row & (cT - 1);
                    float* p = C + ((size_t)(b * HH + h) * cD + d) * cT + t;
                    p[0]  = acc[mi][ni][rr*2];
                    p[cT] = acc[mi][ni][rr*2+1];
                }
            }
        }
    }
}

// ---------------------------------------------------------------------------
__global__ void rope_kernel(float* __restrict__ q, int total_pairs)
{
    int idx = blockIdx.x * blockDim.x + threadIdx.x;
    if (idx >= total_pairs) return;
    const int j   = idx & 63;
    const int row = idx >> 6;
    const int t   = row & (cT - 1);
    const float inv = exp2f(-13.287712379549449f * (float)j * (1.0f / 64.0f));
    const float f = (float)t * inv;
    float sn, cs;
    sincosf(f, &sn, &cs);
    float2 v = *(float2*)(q + (size_t)row * cD + j * 2);
    float2 r;
    r.x = v.x * cs - v.y * sn;
    r.y = v.x * sn + v.y * cs;
    *(float2*)(q + (size_t)row * cD + j * 2) = r;
}

// ---------------------------------------------------------------------------
// TF32 flash attention. BQ=128, BKV=64, 256 thr = 8 warps; warp w owns q-rows
// [16w,16w+16). Q,K,P,V^T all tf32 in smem, conflict-free frag patterns.
// V comes in pre-transposed (b,kvh,d,t). Softmax in exp2 domain.
// ---------------------------------------------------------------------------
__global__ __launch_bounds__(256) void attn_kernel(
    const float* __restrict__ Q, const float* __restrict__ K,
    const float* __restrict__ VT, float* __restrict__ O)
{
    extern __shared__ unsigned sm[];
    unsigned* Qs = sm;                       // [128][132]
    unsigned* Ks = Qs + 128 * 132;           // [64][132]
    unsigned* Vs = Ks + 64 * 132;            // [128][68]  (Vs[d][kv])
    unsigned* Ps = Vs + 128 * 68;            // [128][68]

    const int bid = blockIdx.x;
    const int qb  = bid & 15;                // T/128 = 16 q-blocks
    const int h   = (bid >> 4) & 15;
    const int b   = bid >> 8;
    const int kvh = h >> 1;

    const float* qptr  = Q  + ((size_t)(b * cH + h) * cT + qb * 128) * cD;
    const float* kbase = K  + (size_t)(b * cKVH + kvh) * cT * cD;
    const float* vbase = VT + (size_t)(b * cKVH + kvh) * cD * cT;

    const int tid  = threadIdx.x;
    const int lane = tid & 31;
    const int w    = tid >> 5;
    const int gr   = lane >> 2;
    const int gc   = lane & 3;
    const int wrow = w * 16;                 // warp's q-row base in block

    // Load Q (quantize to tf32), rows [128][128] -> Qs[128][132]
#pragma unroll
    for (int it = 0; it < 16; ++it) {
        const int i = tid + it * 256;
        const int r = i >> 5, c4 = (i & 31) << 2;
        float4 v = *(const float4*)(qptr + (size_t)r * cD + c4);
        uint4 u = make_uint4(f2tf32(v.x), f2tf32(v.y), f2tf32(v.z), f2tf32(v.w));
        *(uint4*)(Qs + r * 132 + c4) = u;
    }

    // softmax state: rows r0 = wrow+gr, r1 = r0+8 (log2 domain)
    float m0 = -1e30f, m1 = -1e30f, l0 = 0.f, l1 = 0.f;
    float oacc[16][4];
#pragma unroll
    for (int ni = 0; ni < 16; ++ni)
#pragma unroll
        for (int c = 0; c < 4; ++c) oacc[ni][c] = 0.f;

    // scale * log2(e)
    const float sc = 0.08838834764831845f * 1.4426950408889634f;
    const int qrow0 = qb * 128;
    const int nkv = 2 * qb + 2;              // kv tiles of 64

    for (int kt = 0; kt < nkv; ++kt) {
        __syncthreads();
        // Load K tile [64][128] -> Ks, V^T tile [128][64] -> Vs
        const float* kp = kbase + (size_t)kt * 64 * cD;
        const float* vp = vbase + kt * 64;
#pragma unroll
        for (int it = 0; it < 8; ++it) {
            const int i = tid + it * 256;
            {   // K
                const int r = i >> 5, c4 = (i & 31) << 2;
                float4 v = *(const float4*)(kp + (size_t)r * cD + c4);
                uint4 u = make_uint4(f2tf32(v.x), f2tf32(v.y), f2tf32(v.z), f2tf32(v.w));
                *(uint4*)(Ks + r * 132 + c4) = u;
            }
            {   // V^T: row d, 64 cols of t
                const int d = i >> 4, c4 = (i & 15) << 2;
                float4 v = *(const float4*)(vp + (size_t)d * cT + c4);
                uint4 u = make_uint4(f2tf32(v.x), f2tf32(v.y), f2tf32(v.z), f2tf32(v.w));
                *(uint4*)(Vs + d * 68 + c4) = u;
            }
        }
        __syncthreads();

        // S = Q K^T : warp computes 16x64; 8 n-frags, k over d=128
        float s[8][4];
#pragma unroll
        for (int ni = 0; ni < 8; ++ni)
#pragma unroll
            for (int c = 0; c < 4; ++c) s[ni][c] = 0.f;

#pragma unroll
        for (int kk = 0; kk < 128; kk += 8) {
            unsigned a0 = Qs[(wrow + gr    ) * 132 + kk + gc    ];
            unsigned a1 = Qs[(wrow + gr + 8) * 132 + kk + gc    ];
            unsigned a2 = Qs[(wrow + gr    ) * 132 + kk + gc + 4];
            unsigned a3 = Qs[(wrow + gr + 8) * 132 + kk + gc + 4];
#pragma unroll
            for (int ni = 0; ni < 8; ++ni) {
                unsigned b0 = Ks[(ni * 8 + gr) * 132 + kk + gc    ];
                unsigned b1 = Ks[(ni * 8 + gr) * 132 + kk + gc + 4];
                asm volatile(
                    "mma.sync.aligned.m16n8k8.row.col.f32.tf32.tf32.f32 "
                    "{%0,%1,%2,%3}, {%4,%5,%6,%7}, {%8,%9}, {%0,%1,%2,%3};"
                    : "+f"(s[ni][0]), "+f"(s[ni][1]), "+f"(s[ni][2]), "+f"(s[ni][3])
                    : "r"(a0), "r"(a1), "r"(a2), "r"(a3), "r"(b0), "r"(b1));
            }
        }

        // scale to log2 domain + causal mask
        const bool diag = (kt >= 2 * qb);
        const int r0g = qrow0 + wrow + gr;
        const int r1g = r0g + 8;
#pragma unroll
        for (int ni = 0; ni < 8; ++ni) {
            const int col = kt * 64 + ni * 8 + gc * 2;
            s[ni][0] = (diag && col     > r0g) ? -1e30f : s[ni][0] * sc;
            s[ni][1] = (diag && col + 1 > r0g) ? -1e30f : s[ni][1] * sc;
            s[ni][2] = (diag && col     > r1g) ? -1e30f : s[ni][2] * sc;
            s[ni][3] = (diag && col + 1 > r1g) ? -1e30f : s[ni][3] * sc;
        }

        // row maxes
        float mx0 = -1e30f, mx1 = -1e30f;
#pragma unroll
        for (int ni = 0; ni < 8; ++ni) {
            mx0 = fmaxf(mx0, fmaxf(s[ni][0], s[ni][1]));
            mx1 = fmaxf(mx1, fmaxf(s[ni][2], s[ni][3]));
        }
        mx0 = fmaxf(mx0, __shfl_xor_sync(0xffffffffu, mx0, 1));
        mx0 = fmaxf(mx0, __shfl_xor_sync(0xffffffffu, mx0, 2));
        mx1 = fmaxf(mx1, __shfl_xor_sync(0xffffffffu, mx1, 1));
        mx1 = fmaxf(mx1, __shfl_xor_sync(0xffffffffu, mx1, 2));

        const float mn0 = fmaxf(m0, mx0);
        const float mn1 = fmaxf(m1, mx1);
        const float cr0 = exp2f(m0 - mn0);
        const float cr1 = exp2f(m1 - mn1);
        m0 = mn0; m1 = mn1;

        float ls0 = 0.f, ls1 = 0.f;
#pragma unroll
        for (int ni = 0; ni < 8; ++ni) {
            float p0 = exp2f(s[ni][0] - mn0);
            float p1 = exp2f(s[ni][1] - mn0);
            float p2 = exp2f(s[ni][2] - mn1);
            float p3 = exp2f(s[ni][3] - mn1);
            ls0 += p0 + p1;
            ls1 += p2 + p3;
            // P -> smem (tf32)
            *(uint2*)(Ps + (wrow + gr    ) * 68 + ni * 8 + gc * 2) =
                make_uint2(f2tf32(p0), f2tf32(p1));
            *(uint2*)(Ps + (wrow + gr + 8) * 68 + ni * 8 + gc * 2) =
                make_uint2(f2tf32(p2), f2tf32(p3));
        }
        ls0 += __shfl_xor_sync(0xffffffffu, ls0, 1);
        ls0 += __shfl_xor_sync(0xffffffffu, ls0, 2);
        ls1 += __shfl_xor_sync(0xffffffffu, ls1, 1);
        ls1 += __shfl_xor_sync(0xffffffffu, ls1, 2);
        l0 = l0 * cr0 + ls0;
        l1 = l1 * cr1 + ls1;

        // rescale O
#pragma unroll
        for (int ni = 0; ni < 16; ++ni) {
            oacc[ni][0] *= cr0; oacc[ni][1] *= cr0;
            oacc[ni][2] *= cr1; oacc[ni][3] *= cr1;
        }
        __syncwarp();

        // O += P V : k over kv=64, 16 n-frags over d=128
#pragma unroll
        for (int kk = 0; kk < 64; kk += 8) {
            unsigned a0 = Ps[(wrow + gr    ) * 68 + kk + gc    ];
            unsigned a1 = Ps[(wrow + gr + 8) * 68 + kk + gc    ];
            unsigned a2 = Ps[(wrow + gr    ) * 68 + kk + gc + 4];
            unsigned a3 = Ps[(wrow + gr + 8) * 68 + kk + gc + 4];
#pragma unroll
            for (int ni = 0; ni < 16; ++ni) {
                unsigned b0 = Vs[(ni * 8 + gr) * 68 + kk + gc    ];
                unsigned b1 = Vs[(ni * 8 + gr) * 68 + kk + gc + 4];
                asm volatile(
                    "mma.sync.aligned.m16n8k8.row.col.f32.tf32.tf32.f32 "
                    "{%0,%1,%2,%3}, {%4,%5,%6,%7}, {%8,%9}, {%0,%1,%2,%3};"
                    : "+f"(oacc[ni][0]), "+f"(oacc[ni][1]),
                      "+f"(oacc[ni][2]), "+f"(oacc[ni][3])
                    : "r"(a0), "r"(a1), "r"(a2), "r"(a3), "r"(b0), "r"(b1));
            }
        }
    }

    // Epilogue: O /= l, write (b,t,h,d)
    const float i0 = 1.f / l0;
    const float i1 = 1.f / l1;
    const int t0 = qrow0 + wrow + gr;
#pragma unroll
    for (int ni = 0; ni < 16; ++ni) {
        const int d = ni * 8 + gc * 2;
        float* p0 = O + ((size_t)(b * cT + t0    ) * cH + h) * cD + d;
        float* p1 = O + ((size_t)(b * cT + t0 + 8) * cH + h) * cD + d;
        *(float2*)p0 = make_float2(oacc[ni][0] * i0, oacc[ni][1] * i0);
        *(float2*)p1 = make_float2(oacc[ni][2] * i1, oacc[ni][3] * i1);
    }
}

// ---------------------------------------------------------------------------
extern "C" void kernel_launch(void* const* d_in, const int* in_sizes, int n_in,
                              void* d_out, int out_size)
{
    const float* x  = (const float*)d_in[0];
    const float* wq = (const float*)d_in[2];
    const float* wk = (const float*)d_in[3];
    const float* wv = (const float*)d_in[4];
    const float* wo = (const float*)d_in[5];
    float* out = (float*)d_out;

    void *pq, *pk, *pv, *pao;
    cudaGetSymbolAddress(&pq, g_q);
    cudaGetSymbolAddress(&pk, g_k);
    cudaGetSymbolAddress(&pv, g_vt);
    cudaGetSymbolAddress(&pao, g_ao);
    float* q  = (float*)pq;
    float* k  = (float*)pk;
    float* vt = (float*)pv;
    float* ao = (float*)pao;

    const int M = cB * cT;  // 4096

    tf32_gemm_kernel<<<dim3(cH * cD / 128, M / 128), 256>>>(x, wq, q, cH * cD, cE, 1, cH);
    tf32_gemm_kernel<<<dim3(cKVH * cD / 128, M / 128), 256>>>(x, wk, k, cKVH * cD, cE, 1, cKVH);
    tf32_gemm_kernel<<<dim3(cKVH * cD / 128, M / 128), 256>>>(x, wv, vt, cKVH * cD, cE, 2, cKVH);

    {
        int tp_q = cB * cH * cT * (cD / 2);
        int tp_k = cB * cKVH * cT * (cD / 2);
        rope_kernel<<<(tp_q + 255) / 256, 256>>>(q, tp_q);
        rope_kernel<<<(tp_k + 255) / 256, 256>>>(k, tp_k);
    }

    const int smem_bytes = (128 * 132 + 64 * 132 + 128 * 68 + 128 * 68) * 4;  // 171008
    cudaFuncSetAttribute(attn_kernel, cudaFuncAttributeMaxDynamicSharedMemorySize, smem_bytes);
    attn_kernel<<<cB * cH * (cT / 128), 256, smem_bytes>>>(q, k, vt, ao);

    tf32_gemm_kernel<<<dim3(cE / 128, M / 128), 256>>>(ao, wo, out, cE, cE, 0, 0);
}

// round 9
// speedup vs baseline: 3.4406x; 1.3749x over previous
#include <cuda_runtime.h>
#include <math.h>
#include <cstdint>

constexpr int cB   = 2;
constexpr int cT   = 2048;
constexpr int cE   = 2048;
constexpr int cH   = 16;
constexpr int cKVH = 8;
constexpr int cD   = 128;

// Scratch (device globals; allocation-free rule)
__device__ float    g_q  [(size_t)cB * cH   * cT * cD];   // (b,h,t,d)
__device__ float    g_k  [(size_t)cB * cKVH * cT * cD];   // (b,kvh,t,d)
__device__ float    g_vt [(size_t)cB * cKVH * cD * cT];   // (b,kvh,d,t)
__device__ unsigned g_aoq[(size_t)cB * cT * cH * cD];     // (b,t,h,d), tf32 bits
__device__ unsigned g_xq [(size_t)cB * cT * cE];          // x, tf32 bits
// Pre-transposed, tf32-quantized weights: WT[n][k] = tf32(W[k][n])
__device__ unsigned g_wqt[(size_t)2048 * 2048];
__device__ unsigned g_wkt[(size_t)1024 * 2048];
__device__ unsigned g_wvt[(size_t)1024 * 2048];
__device__ unsigned g_wot[(size_t)2048 * 2048];

__device__ __forceinline__ unsigned f2tf32(float f) {
    unsigned u;
    asm("cvt.rna.tf32.f32 %0, %1;" : "=r"(u) : "f"(f));
    return u;
}

__device__ __forceinline__ uint32_t smem_u32(const void* p) {
    uint32_t a;
    asm("{ .reg .u64 t; cvta.to.shared.u64 t, %1; cvt.u32.u64 %0, t; }" : "=r"(a) : "l"(p));
    return a;
}

// ---------------------------------------------------------------------------
// Elementwise tf32 quantize: xq[i] = tf32(x[i])
// ---------------------------------------------------------------------------
__global__ __launch_bounds__(256) void quant_kernel(
    const float* __restrict__ x, unsigned* __restrict__ xq)
{
    const size_t i = ((size_t)blockIdx.x * 256 + threadIdx.x) * 4;
    float4 v = *(const float4*)(x + i);
    uint4 u = make_uint4(f2tf32(v.x), f2tf32(v.y), f2tf32(v.z), f2tf32(v.w));
    *(uint4*)(xq + i) = u;
}

// ---------------------------------------------------------------------------
// Weight transpose + tf32 quantize: W[R][Cc] (fp32) -> WT[Cc][R] (tf32 bits)
// ---------------------------------------------------------------------------
__global__ __launch_bounds__(256) void wtrans_kernel(
    const float* __restrict__ W, unsigned* __restrict__ WT, int R, int Cc)
{
    __shared__ unsigned t[32][33];
    const int x = blockIdx.x * 32 + threadIdx.x;
    const int y0 = blockIdx.y * 32 + threadIdx.y;
#pragma unroll
    for (int i = 0; i < 4; ++i)
        t[threadIdx.y + i * 8][threadIdx.x] = f2tf32(W[(size_t)(y0 + i * 8) * Cc + x]);
    __syncthreads();
    const int xo = blockIdx.y * 32 + threadIdx.x;
    const int yo0 = blockIdx.x * 32 + threadIdx.y;
#pragma unroll
    for (int i = 0; i < 4; ++i)
        WT[(size_t)(yo0 + i * 8) * R + xo] = t[threadIdx.x][threadIdx.y + i * 8];
}

// ---------------------------------------------------------------------------
// TF32 mma.sync GEMM v2: C[M,N] = A[M,K] * BT[N,K]^T, A/BT pre-quantized tf32.
// 128x128 tile, K-chunks of 32, 3-stage cp.async pipeline, rotation swizzle.
// 256 thr = 8 warps (2m x 4n), warp 64x32, m16n8k8.
// mode 0: row-major C. mode 1: scatter (b,h,t,d). mode 2: scatter (b,h,d,t).
// ---------------------------------------------------------------------------
__device__ __forceinline__ void gemm_load_stage(
    uint32_t sb, int s, int kt,
    const unsigned* __restrict__ A, const unsigned* __restrict__ BT,
    int rowBase, int colBase, int K, int lr, int lc, int colS)
{
    const uint32_t aBase = sb + (uint32_t)s * 32768u;
    const uint32_t bBase = aBase + 16384u;
#pragma unroll
    for (int c = 0; c < 4; ++c) {
        const int row = lr + c * 32;
        const uint32_t dst = (uint32_t)(row * 32 + colS) * 4u;
        asm volatile("cp.async.cg.shared.global [%0], [%1], 16;"
            :: "r"(aBase + dst), "l"(A + (size_t)(rowBase + row) * K + kt + lc) : "memory");
        asm volatile("cp.async.cg.shared.global [%0], [%1], 16;"
            :: "r"(bBase + dst), "l"(BT + (size_t)(colBase + row) * K + kt + lc) : "memory");
    }
    asm volatile("cp.async.commit_group;" ::: "memory");
}

__global__ __launch_bounds__(256) void tf32_gemm_v2(
    const unsigned* __restrict__ A, const unsigned* __restrict__ BT,
    float* __restrict__ C, int N, int K, int mode, int HH)
{
    extern __shared__ unsigned smp[];          // 3 stages x (A 4096 + B 4096) words
    const uint32_t sb = smem_u32(smp);

    const int tid  = threadIdx.x;
    const int lane = tid & 31;
    const int w    = tid >> 5;
    const int wm   = (w >> 2) * 64;
    const int wn   = (w & 3) * 32;
    const int gr   = lane >> 2;
    const int gc   = lane & 3;
    const int sh   = gr << 2;                  // rotation shift for frag reads

    const int rowBase = blockIdx.y * 128;
    const int colBase = blockIdx.x * 128;

    // cp.async assignment: thread handles rows lr+32c, fixed 16B column lc
    const int lr   = tid >> 3;                 // 0..31
    const int lc   = (tid & 7) * 4;            // 0,4,..,28
    const int colS = (lc + ((lr & 7) << 2)) & 31;

    float acc[4][4][4];
#pragma unroll
    for (int mi = 0; mi < 4; ++mi)
#pragma unroll
        for (int ni = 0; ni < 4; ++ni)
#pragma unroll
            for (int c = 0; c < 4; ++c) acc[mi][ni][c] = 0.f;

    const int nch = K / 32;
    gemm_load_stage(sb, 0, 0,  A, BT, rowBase, colBase, K, lr, lc, colS);
    gemm_load_stage(sb, 1, 32, A, BT, rowBase, colBase, K, lr, lc, colS);

    for (int ck = 0; ck < nch; ++ck) {
        const int s = ck % 3;
        if (ck + 2 < nch)
            asm volatile("cp.async.wait_group 1;" ::: "memory");
        else
            asm volatile("cp.async.wait_group 0;" ::: "memory");
        __syncthreads();
        if (ck + 2 < nch)
            gemm_load_stage(sb, (ck + 2) % 3, (ck + 2) * 32,
                            A, BT, rowBase, colBase, K, lr, lc, colS);

        const unsigned* As = smp + s * 8192;
        const unsigned* Bs = As + 4096;
#pragma unroll
        for (int kk = 0; kk < 32; kk += 8) {
            const int c0 = (kk + gc + sh) & 31;
            const int c1 = (kk + gc + 4 + sh) & 31;
            unsigned af[4][4], bf[4][2];
#pragma unroll
            for (int mi = 0; mi < 4; ++mi) {
                const int r = wm + mi * 16 + gr;
                af[mi][0] = As[r * 32 + c0];
                af[mi][1] = As[(r + 8) * 32 + c0];
                af[mi][2] = As[r * 32 + c1];
                af[mi][3] = As[(r + 8) * 32 + c1];
            }
#pragma unroll
            for (int ni = 0; ni < 4; ++ni) {
                const int rN = wn + ni * 8 + gr;
                bf[ni][0] = Bs[rN * 32 + c0];
                bf[ni][1] = Bs[rN * 32 + c1];
            }
#pragma unroll
            for (int mi = 0; mi < 4; ++mi)
#pragma unroll
                for (int ni = 0; ni < 4; ++ni) {
                    asm volatile(
                        "mma.sync.aligned.m16n8k8.row.col.f32.tf32.tf32.f32 "
                        "{%0,%1,%2,%3}, {%4,%5,%6,%7}, {%8,%9}, {%0,%1,%2,%3};"
                        : "+f"(acc[mi][ni][0]), "+f"(acc[mi][ni][1]),
                          "+f"(acc[mi][ni][2]), "+f"(acc[mi][ni][3])
                        : "r"(af[mi][0]), "r"(af[mi][1]),
                          "r"(af[mi][2]), "r"(af[mi][3]),
                          "r"(bf[ni][0]), "r"(bf[ni][1]));
                }
        }
    }

    // Epilogue
#pragma unroll
    for (int mi = 0; mi < 4; ++mi) {
#pragma unroll
        for (int ni = 0; ni < 4; ++ni) {
            const int row0 = rowBase + wm + mi * 16 + gr;
            const int col  = colBase + wn + ni * 8 + gc * 2;
            if (mode == 0) {
                *(float2*)(C + (size_t)row0 * N + col) =
                    make_float2(acc[mi][ni][0], acc[mi][ni][1]);
                *(float2*)(C + (size_t)(row0 + 8) * N + col) =
                    make_float2(acc[mi][ni][2], acc[mi][ni][3]);
            } else if (mode == 1) {
                const int h = col >> 7;
                const int d = col & (cD - 1);
#pragma unroll
                for (int rr = 0; rr < 2; ++rr) {
                    const int row = row0 + rr * 8;
                    const int b = row >> 11;
                    const int t = row & (cT - 1);
                    float* p = C + ((size_t)(b * HH + h) * cT + t) * cD + d;
                    *(float2*)p = make_float2(acc[mi][ni][rr*2], acc[mi][ni][rr*2+1]);
                }
            } else {  // mode 2: (b,h,d,t)
                const int h = col >> 7;
                const int d = col & (cD - 1);
#pragma unroll
                for (int rr = 0; rr < 2; ++rr) {
                    const int row = row0 + rr * 8;
                    const int b = row >> 11;
                    const int t = row & (cT - 1);
                    float* p = C + ((size_t)(b * HH + h) * cD + d) * cT + t;
                    p[0]  = acc[mi][ni][rr*2];
                    p[cT] = acc[mi][ni][rr*2+1];
                }
            }
        }
    }
}

// ---------------------------------------------------------------------------
__global__ void rope_kernel(float* __restrict__ q, int total_pairs)
{
    int idx = blockIdx.x * blockDim.x + threadIdx.x;
    if (idx >= total_pairs) return;
    const int j   = idx & 63;
    const int row = idx >> 6;
    const int t   = row & (cT - 1);
    const float inv = exp2f(-13.287712379549449f * (float)j * (1.0f / 64.0f));
    const float f = (float)t * inv;
    float sn, cs;
    sincosf(f, &sn, &cs);
    float2 v = *(float2*)(q + (size_t)row * cD + j * 2);
    float2 r;
    r.x = v.x * cs - v.y * sn;
    r.y = v.x * sn + v.y * cs;
    *(float2*)(q + (size_t)row * cD + j * 2) = r;
}

// ---------------------------------------------------------------------------
// TF32 flash attention (R6-proven); epilogue now emits tf32 bits for out-proj.
// ---------------------------------------------------------------------------
__global__ __launch_bounds__(256) void attn_kernel(
    const float* __restrict__ Q, const float* __restrict__ K,
    const float* __restrict__ VT, unsigned* __restrict__ AOq)
{
    extern __shared__ unsigned sm[];
    unsigned* Qs = sm;                       // [128][132]
    unsigned* Ks = Qs + 128 * 132;           // [64][132]
    unsigned* Vs = Ks + 64 * 132;            // [128][68]
    unsigned* Ps = Vs + 128 * 68;            // [128][68]

    const int bid = blockIdx.x;
    const int qb  = bid & 15;
    const int h   = (bid >> 4) & 15;
    const int b   = bid >> 8;
    const int kvh = h >> 1;

    const float* qptr  = Q  + ((size_t)(b * cH + h) * cT + qb * 128) * cD;
    const float* kbase = K  + (size_t)(b * cKVH + kvh) * cT * cD;
    const float* vbase = VT + (size_t)(b * cKVH + kvh) * cD * cT;

    const int tid  = threadIdx.x;
    const int lane = tid & 31;
    const int w    = tid >> 5;
    const int gr   = lane >> 2;
    const int gc   = lane & 3;
    const int wrow = w * 16;

#pragma unroll
    for (int it = 0; it < 16; ++it) {
        const int i = tid + it * 256;
        const int r = i >> 5, c4 = (i & 31) << 2;
        float4 v = *(const float4*)(qptr + (size_t)r * cD + c4);
        uint4 u = make_uint4(f2tf32(v.x), f2tf32(v.y), f2tf32(v.z), f2tf32(v.w));
        *(uint4*)(Qs + r * 132 + c4) = u;
    }

    float m0 = -1e30f, m1 = -1e30f, l0 = 0.f, l1 = 0.f;
    float oacc[16][4];
#pragma unroll
    for (int ni = 0; ni < 16; ++ni)
#pragma unroll
        for (int c = 0; c < 4; ++c) oacc[ni][c] = 0.f;

    const float sc = 0.08838834764831845f * 1.4426950408889634f;
    const int qrow0 = qb * 128;
    const int nkv = 2 * qb + 2;

    for (int kt = 0; kt < nkv; ++kt) {
        __syncthreads();
        const float* kp = kbase + (size_t)kt * 64 * cD;
        const float* vp = vbase + kt * 64;
#pragma unroll
        for (int it = 0; it < 8; ++it) {
            const int i = tid + it * 256;
            {
                const int r = i >> 5, c4 = (i & 31) << 2;
                float4 v = *(const float4*)(kp + (size_t)r * cD + c4);
                uint4 u = make_uint4(f2tf32(v.x), f2tf32(v.y), f2tf32(v.z), f2tf32(v.w));
                *(uint4*)(Ks + r * 132 + c4) = u;
            }
            {
                const int d = i >> 4, c4 = (i & 15) << 2;
                float4 v = *(const float4*)(vp + (size_t)d * cT + c4);
                uint4 u = make_uint4(f2tf32(v.x), f2tf32(v.y), f2tf32(v.z), f2tf32(v.w));
                *(uint4*)(Vs + d * 68 + c4) = u;
            }
        }
        __syncthreads();

        float s[8][4];
#pragma unroll
        for (int ni = 0; ni < 8; ++ni)
#pragma unroll
            for (int c = 0; c < 4; ++c) s[ni][c] = 0.f;

#pragma unroll
        for (int kk = 0; kk < 128; kk += 8) {
            unsigned a0 = Qs[(wrow + gr    ) * 132 + kk + gc    ];
            unsigned a1 = Qs[(wrow + gr + 8) * 132 + kk + gc    ];
            unsigned a2 = Qs[(wrow + gr    ) * 132 + kk + gc + 4];
            unsigned a3 = Qs[(wrow + gr + 8) * 132 + kk + gc + 4];
#pragma unroll
            for (int ni = 0; ni < 8; ++ni) {
                unsigned b0 = Ks[(ni * 8 + gr) * 132 + kk + gc    ];
                unsigned b1 = Ks[(ni * 8 + gr) * 132 + kk + gc + 4];
                asm volatile(
                    "mma.sync.aligned.m16n8k8.row.col.f32.tf32.tf32.f32 "
                    "{%0,%1,%2,%3}, {%4,%5,%6,%7}, {%8,%9}, {%0,%1,%2,%3};"
                    : "+f"(s[ni][0]), "+f"(s[ni][1]), "+f"(s[ni][2]), "+f"(s[ni][3])
                    : "r"(a0), "r"(a1), "r"(a2), "r"(a3), "r"(b0), "r"(b1));
            }
        }

        const bool diag = (kt >= 2 * qb);
        const int r0g = qrow0 + wrow + gr;
        const int r1g = r0g + 8;
#pragma unroll
        for (int ni = 0; ni < 8; ++ni) {
            const int col = kt * 64 + ni * 8 + gc * 2;
            s[ni][0] = (diag && col     > r0g) ? -1e30f : s[ni][0] * sc;
            s[ni][1] = (diag && col + 1 > r0g) ? -1e30f : s[ni][1] * sc;
            s[ni][2] = (diag && col     > r1g) ? -1e30f : s[ni][2] * sc;
            s[ni][3] = (diag && col + 1 > r1g) ? -1e30f : s[ni][3] * sc;
        }

        float mx0 = -1e30f, mx1 = -1e30f;
#pragma unroll
        for (int ni = 0; ni < 8; ++ni) {
            mx0 = fmaxf(mx0, fmaxf(s[ni][0], s[ni][1]));
            mx1 = fmaxf(mx1, fmaxf(s[ni][2], s[ni][3]));
        }
        mx0 = fmaxf(mx0, __shfl_xor_sync(0xffffffffu, mx0, 1));
        mx0 = fmaxf(mx0, __shfl_xor_sync(0xffffffffu, mx0, 2));
        mx1 = fmaxf(mx1, __shfl_xor_sync(0xffffffffu, mx1, 1));
        mx1 = fmaxf(mx1, __shfl_xor_sync(0xffffffffu, mx1, 2));

        const float mn0 = fmaxf(m0, mx0);
        const float mn1 = fmaxf(m1, mx1);
        const float cr0 = exp2f(m0 - mn0);
        const float cr1 = exp2f(m1 - mn1);
        m0 = mn0; m1 = mn1;

        float ls0 = 0.f, ls1 = 0.f;
#pragma unroll
        for (int ni = 0; ni < 8; ++ni) {
            float p0 = exp2f(s[ni][0] - mn0);
            float p1 = exp2f(s[ni][1] - mn0);
            float p2 = exp2f(s[ni][2] - mn1);
            float p3 = exp2f(s[ni][3] - mn1);
            ls0 += p0 + p1;
            ls1 += p2 + p3;
            *(uint2*)(Ps + (wrow + gr    ) * 68 + ni * 8 + gc * 2) =
                make_uint2(f2tf32(p0), f2tf32(p1));
            *(uint2*)(Ps + (wrow + gr + 8) * 68 + ni * 8 + gc * 2) =
                make_uint2(f2tf32(p2), f2tf32(p3));
        }
        ls0 += __shfl_xor_sync(0xffffffffu, ls0, 1);
        ls0 += __shfl_xor_sync(0xffffffffu, ls0, 2);
        ls1 += __shfl_xor_sync(0xffffffffu, ls1, 1);
        ls1 += __shfl_xor_sync(0xffffffffu, ls1, 2);
        l0 = l0 * cr0 + ls0;
        l1 = l1 * cr1 + ls1;

#pragma unroll
        for (int ni = 0; ni < 16; ++ni) {
            oacc[ni][0] *= cr0; oacc[ni][1] *= cr0;
            oacc[ni][2] *= cr1; oacc[ni][3] *= cr1;
        }
        __syncwarp();

#pragma unroll
        for (int kk = 0; kk < 64; kk += 8) {
            unsigned a0 = Ps[(wrow + gr    ) * 68 + kk + gc    ];
            unsigned a1 = Ps[(wrow + gr + 8) * 68 + kk + gc    ];
            unsigned a2 = Ps[(wrow + gr    ) * 68 + kk + gc + 4];
            unsigned a3 = Ps[(wrow + gr + 8) * 68 + kk + gc + 4];
#pragma unroll
            for (int ni = 0; ni < 16; ++ni) {
                unsigned b0 = Vs[(ni * 8 + gr) * 68 + kk + gc    ];
                unsigned b1 = Vs[(ni * 8 + gr) * 68 + kk + gc + 4];
                asm volatile(
                    "mma.sync.aligned.m16n8k8.row.col.f32.tf32.tf32.f32 "
                    "{%0,%1,%2,%3}, {%4,%5,%6,%7}, {%8,%9}, {%0,%1,%2,%3};"
                    : "+f"(oacc[ni][0]), "+f"(oacc[ni][1]),
                      "+f"(oacc[ni][2]), "+f"(oacc[ni][3])
                    : "r"(a0), "r"(a1), "r"(a2), "r"(a3), "r"(b0), "r"(b1));
            }
        }
    }

    // Epilogue: O /= l, quantize to tf32 bits, write (b,t,h,d)
    const float i0 = 1.f / l0;
    const float i1 = 1.f / l1;
    const int t0 = qrow0 + wrow + gr;
#pragma unroll
    for (int ni = 0; ni < 16; ++ni) {
        const int d = ni * 8 + gc * 2;
        unsigned* p0 = AOq + ((size_t)(b * cT + t0    ) * cH + h) * cD + d;
        unsigned* p1 = AOq + ((size_t)(b * cT + t0 + 8) * cH + h) * cD + d;
        *(uint2*)p0 = make_uint2(f2tf32(oacc[ni][0] * i0), f2tf32(oacc[ni][1] * i0));
        *(uint2*)p1 = make_uint2(f2tf32(oacc[ni][2] * i1), f2tf32(oacc[ni][3] * i1));
    }
}

// ---------------------------------------------------------------------------
extern "C" void kernel_launch(void* const* d_in, const int* in_sizes, int n_in,
                              void* d_out, int out_size)
{
    const float* x  = (const float*)d_in[0];
    const float* wq = (const float*)d_in[2];
    const float* wk = (const float*)d_in[3];
    const float* wv = (const float*)d_in[4];
    const float* wo = (const float*)d_in[5];
    float* out = (float*)d_out;

    void *pq, *pk, *pv, *pao, *pxq, *pwq, *pwk, *pwv, *pwo;
    cudaGetSymbolAddress(&pq,  g_q);
    cudaGetSymbolAddress(&pk,  g_k);
    cudaGetSymbolAddress(&pv,  g_vt);
    cudaGetSymbolAddress(&pao, g_aoq);
    cudaGetSymbolAddress(&pxq, g_xq);
    cudaGetSymbolAddress(&pwq, g_wqt);
    cudaGetSymbolAddress(&pwk, g_wkt);
    cudaGetSymbolAddress(&pwv, g_wvt);
    cudaGetSymbolAddress(&pwo, g_wot);
    float* q  = (float*)pq;
    float* k  = (float*)pk;
    float* vt = (float*)pv;
    unsigned* aoq = (unsigned*)pao;
    unsigned* xq  = (unsigned*)pxq;
    unsigned* wqt = (unsigned*)pwq;
    unsigned* wkt = (unsigned*)pwk;
    unsigned* wvt = (unsigned*)pwv;
    unsigned* wot = (unsigned*)pwo;

    const int M = cB * cT;  // 4096

    // Pre-quantize x; transpose+quantize weights
    quant_kernel<<<(int)(((size_t)M * cE / 4) / 256), 256>>>(x, xq);
    wtrans_kernel<<<dim3(2048 / 32, 2048 / 32), dim3(32, 8)>>>(wq, wqt, 2048, 2048);
    wtrans_kernel<<<dim3(1024 / 32, 2048 / 32), dim3(32, 8)>>>(wk, wkt, 2048, 1024);
    wtrans_kernel<<<dim3(1024 / 32, 2048 / 32), dim3(32, 8)>>>(wv, wvt, 2048, 1024);
    wtrans_kernel<<<dim3(2048 / 32, 2048 / 32), dim3(32, 8)>>>(wo, wot, 2048, 2048);

    const int gemm_smem = 3 * 32768;  // 98304
    cudaFuncSetAttribute(tf32_gemm_v2, cudaFuncAttributeMaxDynamicSharedMemorySize, gemm_smem);

    // QKV projections
    tf32_gemm_v2<<<dim3(16, 32), 256, gemm_smem>>>(xq, wqt, q,  cH * cD,   cE, 1, cH);
    tf32_gemm_v2<<<dim3(8, 32),  256, gemm_smem>>>(xq, wkt, k,  cKVH * cD, cE, 1, cKVH);
    tf32_gemm_v2<<<dim3(8, 32),  256, gemm_smem>>>(xq, wvt, vt, cKVH * cD, cE, 2, cKVH);

    {
        int tp_q = cB * cH * cT * (cD / 2);
        int tp_k = cB * cKVH * cT * (cD / 2);
        rope_kernel<<<(tp_q + 255) / 256, 256>>>(q, tp_q);
        rope_kernel<<<(tp_k + 255) / 256, 256>>>(k, tp_k);
    }

    const int attn_smem = (128 * 132 + 64 * 132 + 128 * 68 + 128 * 68) * 4;  // 171008
    cudaFuncSetAttribute(attn_kernel, cudaFuncAttributeMaxDynamicSharedMemorySize, attn_smem);
    attn_kernel<<<cB * cH * (cT / 128), 256, attn_smem>>>(q, k, vt, aoq);

    // Output projection
    tf32_gemm_v2<<<dim3(16, 32), 256, gemm_smem>>>(aoq, wot, out, cE, cE, 0, 0);
}

// round 10
// speedup vs baseline: 3.7348x; 1.0855x over previous
#include <cuda_runtime.h>
#include <math.h>
#include <cstdint>

constexpr int cB   = 2;
constexpr int cT   = 2048;
constexpr int cE   = 2048;
constexpr int cH   = 16;
constexpr int cKVH = 8;
constexpr int cD   = 128;

// Scratch (device globals; allocation-free rule). q/k/vt hold tf32 bits.
__device__ unsigned g_q  [(size_t)cB * cH   * cT * cD];   // (b,h,t,d) roped tf32
__device__ unsigned g_k  [(size_t)cB * cKVH * cT * cD];   // (b,kvh,t,d) roped tf32
__device__ unsigned g_vt [(size_t)cB * cKVH * cD * cT];   // (b,kvh,d,t) tf32
__device__ unsigned g_aoq[(size_t)cB * cT * cH * cD];     // (b,t,h,d) tf32
__device__ unsigned g_xq [(size_t)cB * cT * cE];          // x tf32
// Pre-transposed, tf32-quantized weights: WT[n][k] = tf32(W[k][n])
__device__ unsigned g_wqt[(size_t)2048 * 2048];
__device__ unsigned g_wkt[(size_t)1024 * 2048];
__device__ unsigned g_wvt[(size_t)1024 * 2048];
__device__ unsigned g_wot[(size_t)2048 * 2048];

__device__ __forceinline__ unsigned f2tf32(float f) {
    unsigned u;
    asm("cvt.rna.tf32.f32 %0, %1;" : "=r"(u) : "f"(f));
    return u;
}

__device__ __forceinline__ uint32_t smem_u32(const void* p) {
    uint32_t a;
    asm("{ .reg .u64 t; cvta.to.shared.u64 t, %1; cvt.u32.u64 %0, t; }" : "=r"(a) : "l"(p));
    return a;
}

__device__ __forceinline__ void cp16(uint32_t dst, const void* src) {
    asm volatile("cp.async.cg.shared.global [%0], [%1], 16;"
                 :: "r"(dst), "l"(src) : "memory");
}

// ---------------------------------------------------------------------------
__global__ __launch_bounds__(256) void quant_kernel(
    const float* __restrict__ x, unsigned* __restrict__ xq)
{
    const size_t i = ((size_t)blockIdx.x * 256 + threadIdx.x) * 4;
    float4 v = *(const float4*)(x + i);
    uint4 u = make_uint4(f2tf32(v.x), f2tf32(v.y), f2tf32(v.z), f2tf32(v.w));
    *(uint4*)(xq + i) = u;
}

// ---------------------------------------------------------------------------
__global__ __launch_bounds__(256) void wtrans_kernel(
    const float* __restrict__ W, unsigned* __restrict__ WT, int R, int Cc)
{
    __shared__ unsigned t[32][33];
    const int x = blockIdx.x * 32 + threadIdx.x;
    const int y0 = blockIdx.y * 32 + threadIdx.y;
#pragma unroll
    for (int i = 0; i < 4; ++i)
        t[threadIdx.y + i * 8][threadIdx.x] = f2tf32(W[(size_t)(y0 + i * 8) * Cc + x]);
    __syncthreads();
    const int xo = blockIdx.y * 32 + threadIdx.x;
    const int yo0 = blockIdx.x * 32 + threadIdx.y;
#pragma unroll
    for (int i = 0; i < 4; ++i)
        WT[(size_t)(yo0 + i * 8) * R + xo] = t[threadIdx.x][threadIdx.y + i * 8];
}

// ---------------------------------------------------------------------------
// TF32 mma.sync GEMM v3: C = A[M,K] * BT[N,K]^T, inputs pre-quantized tf32.
// CTA tile 256x128, warp tile 64x64 (8 warps 4m x 2n), K-chunks of 32,
// 3-stage cp.async pipeline, rotation swizzle.
// mode 0: row-major fp32. mode 1: rope + scatter (b,h,t,d) tf32 bits.
// mode 2: scatter (b,h,d,t) tf32 bits.
// ---------------------------------------------------------------------------
__device__ __forceinline__ void gemm3_load_stage(
    uint32_t sb, int s, int kt,
    const unsigned* __restrict__ A, const unsigned* __restrict__ BT,
    int rowBase, int colBase, int K, int lr, int lc, int colS)
{
    const uint32_t aBase = sb + (uint32_t)s * 49152u;
    const uint32_t bBase = aBase + 32768u;
#pragma unroll
    for (int c = 0; c < 8; ++c) {
        const int row = lr + c * 32;
        cp16(aBase + (uint32_t)(row * 32 + colS) * 4u,
             A + (size_t)(rowBase + row) * K + kt + lc);
    }
#pragma unroll
    for (int c = 0; c < 4; ++c) {
        const int row = lr + c * 32;
        cp16(bBase + (uint32_t)(row * 32 + colS) * 4u,
             BT + (size_t)(colBase + row) * K + kt + lc);
    }
    asm volatile("cp.async.commit_group;" ::: "memory");
}

__global__ __launch_bounds__(256) void tf32_gemm_v3(
    const unsigned* __restrict__ A, const unsigned* __restrict__ BT,
    void* __restrict__ Cv, int N, int K, int mode, int HH)
{
    extern __shared__ unsigned smp[];      // 3 stages x (A 8192 + B 4096) words
    const uint32_t sb = smem_u32(smp);

    const int tid  = threadIdx.x;
    const int lane = tid & 31;
    const int w    = tid >> 5;
    const int wm   = (w >> 1) * 64;        // 0,64,128,192
    const int wn   = (w & 1) * 64;         // 0,64
    const int gr   = lane >> 2;
    const int gc   = lane & 3;
    const int sh   = gr << 2;

    const int rowBase = blockIdx.y * 256;
    const int colBase = blockIdx.x * 128;

    const int lr   = tid >> 3;             // 0..31
    const int lc   = (tid & 7) * 4;        // 0..28
    const int colS = (lc + ((lr & 7) << 2)) & 31;

    float acc[4][8][4];
#pragma unroll
    for (int mi = 0; mi < 4; ++mi)
#pragma unroll
        for (int ni = 0; ni < 8; ++ni)
#pragma unroll
            for (int c = 0; c < 4; ++c) acc[mi][ni][c] = 0.f;

    const int nch = K / 32;
    gemm3_load_stage(sb, 0, 0,  A, BT, rowBase, colBase, K, lr, lc, colS);
    gemm3_load_stage(sb, 1, 32, A, BT, rowBase, colBase, K, lr, lc, colS);

    for (int ck = 0; ck < nch; ++ck) {
        const int s = ck % 3;
        if (ck + 2 < nch)
            asm volatile("cp.async.wait_group 1;" ::: "memory");
        else
            asm volatile("cp.async.wait_group 0;" ::: "memory");
        __syncthreads();
        if (ck + 2 < nch)
            gemm3_load_stage(sb, (ck + 2) % 3, (ck + 2) * 32,
                             A, BT, rowBase, colBase, K, lr, lc, colS);

        const unsigned* As = smp + s * 12288;
        const unsigned* Bs = As + 8192;
#pragma unroll
        for (int kk = 0; kk < 32; kk += 8) {
            const int c0 = (kk + gc + sh) & 31;
            const int c1 = (kk + gc + 4 + sh) & 31;
            unsigned af[4][4], bf[8][2];
#pragma unroll
            for (int mi = 0; mi < 4; ++mi) {
                const int r = wm + mi * 16 + gr;
                af[mi][0] = As[r * 32 + c0];
                af[mi][1] = As[(r + 8) * 32 + c0];
                af[mi][2] = As[r * 32 + c1];
                af[mi][3] = As[(r + 8) * 32 + c1];
            }
#pragma unroll
            for (int ni = 0; ni < 8; ++ni) {
                const int rN = wn + ni * 8 + gr;
                bf[ni][0] = Bs[rN * 32 + c0];
                bf[ni][1] = Bs[rN * 32 + c1];
            }
#pragma unroll
            for (int mi = 0; mi < 4; ++mi)
#pragma unroll
                for (int ni = 0; ni < 8; ++ni) {
                    asm volatile(
                        "mma.sync.aligned.m16n8k8.row.col.f32.tf32.tf32.f32 "
                        "{%0,%1,%2,%3}, {%4,%5,%6,%7}, {%8,%9}, {%0,%1,%2,%3};"
                        : "+f"(acc[mi][ni][0]), "+f"(acc[mi][ni][1]),
                          "+f"(acc[mi][ni][2]), "+f"(acc[mi][ni][3])
                        : "r"(af[mi][0]), "r"(af[mi][1]),
                          "r"(af[mi][2]), "r"(af[mi][3]),
                          "r"(bf[ni][0]), "r"(bf[ni][1]));
                }
        }
    }

    // Epilogue
#pragma unroll
    for (int mi = 0; mi < 4; ++mi) {
#pragma unroll
        for (int ni = 0; ni < 8; ++ni) {
            const int row0 = rowBase + wm + mi * 16 + gr;
            const int col  = colBase + wn + ni * 8 + gc * 2;
            if (mode == 0) {
                float* C = (float*)Cv;
                *(float2*)(C + (size_t)row0 * N + col) =
                    make_float2(acc[mi][ni][0], acc[mi][ni][1]);
                *(float2*)(C + (size_t)(row0 + 8) * N + col) =
                    make_float2(acc[mi][ni][2], acc[mi][ni][3]);
            } else if (mode == 1) {  // rope + tf32 scatter (b,h,t,d)
                unsigned* C = (unsigned*)Cv;
                const int h = col >> 7;
                const int d = col & (cD - 1);
                const int j = d >> 1;
                const float inv = exp2f(-13.287712379549449f * (float)j * (1.0f / 64.0f));
#pragma unroll
                for (int rr = 0; rr < 2; ++rr) {
                    const int row = row0 + rr * 8;
                    const int b = row >> 11;
                    const int t = row & (cT - 1);
                    float sn, cs;
                    sincosf((float)t * inv, &sn, &cs);
                    const float x0 = acc[mi][ni][rr*2];
                    const float x1 = acc[mi][ni][rr*2+1];
                    unsigned* p = C + ((size_t)(b * HH + h) * cT + t) * cD + d;
                    *(uint2*)p = make_uint2(f2tf32(x0 * cs - x1 * sn),
                                            f2tf32(x0 * sn + x1 * cs));
                }
            } else {  // mode 2: tf32 scatter (b,h,d,t)
                unsigned* C = (unsigned*)Cv;
                const int h = col >> 7;
                const int d = col & (cD - 1);
#pragma unroll
                for (int rr = 0; rr < 2; ++rr) {
                    const int row = row0 + rr * 8;
                    const int b = row >> 11;
                    const int t = row & (cT - 1);
                    unsigned* p = C + ((size_t)(b * HH + h) * cD + d) * cT + t;
                    p[0]  = f2tf32(acc[mi][ni][rr*2]);
                    p[cT] = f2tf32(acc[mi][ni][rr*2+1]);
                }
            }
        }
    }
}

// ---------------------------------------------------------------------------
// TF32 flash attention. Inputs are tf32 bits; fills are pure cp.async.
// ---------------------------------------------------------------------------
__global__ __launch_bounds__(256) void attn_kernel(
    const unsigned* __restrict__ Q, const unsigned* __restrict__ K,
    const unsigned* __restrict__ VT, unsigned* __restrict__ AOq)
{
    extern __shared__ unsigned sm[];
    unsigned* Qs = sm;                       // [128][132]
    unsigned* Ks = Qs + 128 * 132;           // [64][132]
    unsigned* Vs = Ks + 64 * 132;            // [128][68]
    unsigned* Ps = Vs + 128 * 68;            // [128][68]
    const uint32_t sQ = smem_u32(Qs);
    const uint32_t sK = smem_u32(Ks);
    const uint32_t sV = smem_u32(Vs);

    const int bid = blockIdx.x;
    const int qb  = bid & 15;
    const int h   = (bid >> 4) & 15;
    const int b   = bid >> 8;
    const int kvh = h >> 1;

    const unsigned* qptr  = Q  + ((size_t)(b * cH + h) * cT + qb * 128) * cD;
    const unsigned* kbase = K  + (size_t)(b * cKVH + kvh) * cT * cD;
    const unsigned* vbase = VT + (size_t)(b * cKVH + kvh) * cD * cT;

    const int tid  = threadIdx.x;
    const int lane = tid & 31;
    const int w    = tid >> 5;
    const int gr   = lane >> 2;
    const int gc   = lane & 3;
    const int wrow = w * 16;

    // Q fill via cp.async
#pragma unroll
    for (int it = 0; it < 16; ++it) {
        const int i = tid + it * 256;
        const int r = i >> 5, c4 = (i & 31) << 2;
        cp16(sQ + (uint32_t)(r * 132 + c4) * 4u, qptr + (size_t)r * cD + c4);
    }
    asm volatile("cp.async.commit_group;" ::: "memory");

    float m0 = -1e30f, m1 = -1e30f, l0 = 0.f, l1 = 0.f;
    float oacc[16][4];
#pragma unroll
    for (int ni = 0; ni < 16; ++ni)
#pragma unroll
        for (int c = 0; c < 4; ++c) oacc[ni][c] = 0.f;

    const float sc = 0.08838834764831845f * 1.4426950408889634f;
    const int qrow0 = qb * 128;
    const int nkv = 2 * qb + 2;

    for (int kt = 0; kt < nkv; ++kt) {
        __syncthreads();  // previous tile's PV done
        const unsigned* kp = kbase + (size_t)kt * 64 * cD;
        const unsigned* vp = vbase + kt * 64;
#pragma unroll
        for (int it = 0; it < 8; ++it) {
            const int i = tid + it * 256;
            {
                const int r = i >> 5, c4 = (i & 31) << 2;
                cp16(sK + (uint32_t)(r * 132 + c4) * 4u, kp + (size_t)r * cD + c4);
            }
            {
                const int d = i >> 4, c4 = (i & 15) << 2;
                cp16(sV + (uint32_t)(d * 68 + c4) * 4u, vp + (size_t)d * cT + c4);
            }
        }
        asm volatile("cp.async.commit_group;" ::: "memory");
        asm volatile("cp.async.wait_group 0;" ::: "memory");
        __syncthreads();

        float s[8][4];
#pragma unroll
        for (int ni = 0; ni < 8; ++ni)
#pragma unroll
            for (int c = 0; c < 4; ++c) s[ni][c] = 0.f;

#pragma unroll
        for (int kk = 0; kk < 128; kk += 8) {
            unsigned a0 = Qs[(wrow + gr    ) * 132 + kk + gc    ];
            unsigned a1 = Qs[(wrow + gr + 8) * 132 + kk + gc    ];
            unsigned a2 = Qs[(wrow + gr    ) * 132 + kk + gc + 4];
            unsigned a3 = Qs[(wrow + gr + 8) * 132 + kk + gc + 4];
#pragma unroll
            for (int ni = 0; ni < 8; ++ni) {
                unsigned b0 = Ks[(ni * 8 + gr) * 132 + kk + gc    ];
                unsigned b1 = Ks[(ni * 8 + gr) * 132 + kk + gc + 4];
                asm volatile(
                    "mma.sync.aligned.m16n8k8.row.col.f32.tf32.tf32.f32 "
                    "{%0,%1,%2,%3}, {%4,%5,%6,%7}, {%8,%9}, {%0,%1,%2,%3};"
                    : "+f"(s[ni][0]), "+f"(s[ni][1]), "+f"(s[ni][2]), "+f"(s[ni][3])
                    : "r"(a0), "r"(a1), "r"(a2), "r"(a3), "r"(b0), "r"(b1));
            }
        }

        const bool diag = (kt >= 2 * qb);
        const int r0g = qrow0 + wrow + gr;
        const int r1g = r0g + 8;
#pragma unroll
        for (int ni = 0; ni < 8; ++ni) {
            const int col = kt * 64 + ni * 8 + gc * 2;
            s[ni][0] = (diag && col     > r0g) ? -1e30f : s[ni][0] * sc;
            s[ni][1] = (diag && col + 1 > r0g) ? -1e30f : s[ni][1] * sc;
            s[ni][2] = (diag && col     > r1g) ? -1e30f : s[ni][2] * sc;
            s[ni][3] = (diag && col + 1 > r1g) ? -1e30f : s[ni][3] * sc;
        }

        float mx0 = -1e30f, mx1 = -1e30f;
#pragma unroll
        for (int ni = 0; ni < 8; ++ni) {
            mx0 = fmaxf(mx0, fmaxf(s[ni][0], s[ni][1]));
            mx1 = fmaxf(mx1, fmaxf(s[ni][2], s[ni][3]));
        }
        mx0 = fmaxf(mx0, __shfl_xor_sync(0xffffffffu, mx0, 1));
        mx0 = fmaxf(mx0, __shfl_xor_sync(0xffffffffu, mx0, 2));
        mx1 = fmaxf(mx1, __shfl_xor_sync(0xffffffffu, mx1, 1));
        mx1 = fmaxf(mx1, __shfl_xor_sync(0xffffffffu, mx1, 2));

        const float mn0 = fmaxf(m0, mx0);
        const float mn1 = fmaxf(m1, mx1);
        const float cr0 = exp2f(m0 - mn0);
        const float cr1 = exp2f(m1 - mn1);
        m0 = mn0; m1 = mn1;

        float ls0 = 0.f, ls1 = 0.f;
#pragma unroll
        for (int ni = 0; ni < 8; ++ni) {
            float p0 = exp2f(s[ni][0] - mn0);
            float p1 = exp2f(s[ni][1] - mn0);
            float p2 = exp2f(s[ni][2] - mn1);
            float p3 = exp2f(s[ni][3] - mn1);
            ls0 += p0 + p1;
            ls1 += p2 + p3;
            *(uint2*)(Ps + (wrow + gr    ) * 68 + ni * 8 + gc * 2) =
                make_uint2(f2tf32(p0), f2tf32(p1));
            *(uint2*)(Ps + (wrow + gr + 8) * 68 + ni * 8 + gc * 2) =
                make_uint2(f2tf32(p2), f2tf32(p3));
        }
        ls0 += __shfl_xor_sync(0xffffffffu, ls0, 1);
        ls0 += __shfl_xor_sync(0xffffffffu, ls0, 2);
        ls1 += __shfl_xor_sync(0xffffffffu, ls1, 1);
        ls1 += __shfl_xor_sync(0xffffffffu, ls1, 2);
        l0 = l0 * cr0 + ls0;
        l1 = l1 * cr1 + ls1;

#pragma unroll
        for (int ni = 0; ni < 16; ++ni) {
            oacc[ni][0] *= cr0; oacc[ni][1] *= cr0;
            oacc[ni][2] *= cr1; oacc[ni][3] *= cr1;
        }
        __syncwarp();

#pragma unroll
        for (int kk = 0; kk < 64; kk += 8) {
            unsigned a0 = Ps[(wrow + gr    ) * 68 + kk + gc    ];
            unsigned a1 = Ps[(wrow + gr + 8) * 68 + kk + gc    ];
            unsigned a2 = Ps[(wrow + gr    ) * 68 + kk + gc + 4];
            unsigned a3 = Ps[(wrow + gr + 8) * 68 + kk + gc + 4];
#pragma unroll
            for (int ni = 0; ni < 16; ++ni) {
                unsigned b0 = Vs[(ni * 8 + gr) * 68 + kk + gc    ];
                unsigned b1 = Vs[(ni * 8 + gr) * 68 + kk + gc + 4];
                asm volatile(
                    "mma.sync.aligned.m16n8k8.row.col.f32.tf32.tf32.f32 "
                    "{%0,%1,%2,%3}, {%4,%5,%6,%7}, {%8,%9}, {%0,%1,%2,%3};"
                    : "+f"(oacc[ni][0]), "+f"(oacc[ni][1]),
                      "+f"(oacc[ni][2]), "+f"(oacc[ni][3])
                    : "r"(a0), "r"(a1), "r"(a2), "r"(a3), "r"(b0), "r"(b1));
            }
        }
    }

    const float i0 = 1.f / l0;
    const float i1 = 1.f / l1;
    const int t0 = qrow0 + wrow + gr;
#pragma unroll
    for (int ni = 0; ni < 16; ++ni) {
        const int d = ni * 8 + gc * 2;
        unsigned* p0 = AOq + ((size_t)(b * cT + t0    ) * cH + h) * cD + d;
        unsigned* p1 = AOq + ((size_t)(b * cT + t0 + 8) * cH + h) * cD + d;
        *(uint2*)p0 = make_uint2(f2tf32(oacc[ni][0] * i0), f2tf32(oacc[ni][1] * i0));
        *(uint2*)p1 = make_uint2(f2tf32(oacc[ni][2] * i1), f2tf32(oacc[ni][3] * i1));
    }
}

// ---------------------------------------------------------------------------
extern "C" void kernel_launch(void* const* d_in, const int* in_sizes, int n_in,
                              void* d_out, int out_size)
{
    const float* x  = (const float*)d_in[0];
    const float* wq = (const float*)d_in[2];
    const float* wk = (const float*)d_in[3];
    const float* wv = (const float*)d_in[4];
    const float* wo = (const float*)d_in[5];
    float* out = (float*)d_out;

    void *pq, *pk, *pv, *pao, *pxq, *pwq, *pwk, *pwv, *pwo;
    cudaGetSymbolAddress(&pq,  g_q);
    cudaGetSymbolAddress(&pk,  g_k);
    cudaGetSymbolAddress(&pv,  g_vt);
    cudaGetSymbolAddress(&pao, g_aoq);
    cudaGetSymbolAddress(&pxq, g_xq);
    cudaGetSymbolAddress(&pwq, g_wqt);
    cudaGetSymbolAddress(&pwk, g_wkt);
    cudaGetSymbolAddress(&pwv, g_wvt);
    cudaGetSymbolAddress(&pwo, g_wot);
    unsigned* q   = (unsigned*)pq;
    unsigned* k   = (unsigned*)pk;
    unsigned* vt  = (unsigned*)pv;
    unsigned* aoq = (unsigned*)pao;
    unsigned* xq  = (unsigned*)pxq;
    unsigned* wqt = (unsigned*)pwq;
    unsigned* wkt = (unsigned*)pwk;
    unsigned* wvt = (unsigned*)pwv;
    unsigned* wot = (unsigned*)pwo;

    const int M = cB * cT;  // 4096

    quant_kernel<<<(int)(((size_t)M * cE / 4) / 256), 256>>>(x, xq);
    wtrans_kernel<<<dim3(2048 / 32, 2048 / 32), dim3(32, 8)>>>(wq, wqt, 2048, 2048);
    wtrans_kernel<<<dim3(1024 / 32, 2048 / 32), dim3(32, 8)>>>(wk, wkt, 2048, 1024);
    wtrans_kernel<<<dim3(1024 / 32, 2048 / 32), dim3(32, 8)>>>(wv, wvt, 2048, 1024);
    wtrans_kernel<<<dim3(2048 / 32, 2048 / 32), dim3(32, 8)>>>(wo, wot, 2048, 2048);

    const int gemm_smem = 3 * 49152;  // 147456
    cudaFuncSetAttribute(tf32_gemm_v3, cudaFuncAttributeMaxDynamicSharedMemorySize, gemm_smem);

    // QKV projections (rope fused into q/k epilogues)
    tf32_gemm_v3<<<dim3(16, 16), 256, gemm_smem>>>(xq, wqt, q,  cH * cD,   cE, 1, cH);
    tf32_gemm_v3<<<dim3(8, 16),  256, gemm_smem>>>(xq, wkt, k,  cKVH * cD, cE, 1, cKVH);
    tf32_gemm_v3<<<dim3(8, 16),  256, gemm_smem>>>(xq, wvt, vt, cKVH * cD, cE, 2, cKVH);

    const int attn_smem = (128 * 132 + 64 * 132 + 128 * 68 + 128 * 68) * 4;  // 171008
    cudaFuncSetAttribute(attn_kernel, cudaFuncAttributeMaxDynamicSharedMemorySize, attn_smem);
    attn_kernel<<<cB * cH * (cT / 128), 256, attn_smem>>>(q, k, vt, aoq);

    // Output projection
    tf32_gemm_v3<<<dim3(16, 16), 256, gemm_smem>>>(aoq, wot, out, cE, cE, 0, 0);
}

// round 12
// speedup vs baseline: 6.1774x; 1.6540x over previous
#include <cuda_runtime.h>
#include <cuda_fp16.h>
#include <math.h>
#include <cstdint>

constexpr int cB   = 2;
constexpr int cT   = 2048;
constexpr int cE   = 2048;
constexpr int cH   = 16;
constexpr int cKVH = 8;
constexpr int cD   = 128;

// Scratch (device globals). Half-precision operand buffers.
__device__ __half g_q  [(size_t)cB * cH   * cT * cD];   // (b,h,t,d) roped
__device__ __half g_k  [(size_t)cB * cKVH * cT * cD];   // (b,kvh,t,d) roped
__device__ __half g_vt [(size_t)cB * cKVH * cD * cT];   // (b,kvh,d,t)
__device__ __half g_ao [(size_t)cB * cT * cH * cD];     // (b,t,h,d)
__device__ __half g_xh [(size_t)cB * cT * cE];          // x in half
// Pre-transposed half weights: WT[n][k] = half(W[k][n])
__device__ __half g_wqt[(size_t)2048 * 2048];
__device__ __half g_wkt[(size_t)1024 * 2048];
__device__ __half g_wvt[(size_t)1024 * 2048];
__device__ __half g_wot[(size_t)2048 * 2048];

__device__ __forceinline__ uint32_t smem_u32(const void* p) {
    uint32_t a;
    asm("{ .reg .u64 t; cvta.to.shared.u64 t, %1; cvt.u32.u64 %0, t; }" : "=r"(a) : "l"(p));
    return a;
}

__device__ __forceinline__ void cp16(uint32_t dst, const void* src) {
    asm volatile("cp.async.cg.shared.global [%0], [%1], 16;"
                 :: "r"(dst), "l"(src) : "memory");
}

__device__ __forceinline__ unsigned packh2(float a, float b) {
    __half2 h = __floats2half2_rn(a, b);
    return *(unsigned*)&h;
}

// ---------------------------------------------------------------------------
__global__ __launch_bounds__(256) void quant_kernel(
    const float* __restrict__ x, __half* __restrict__ xh)
{
    const size_t i = ((size_t)blockIdx.x * 256 + threadIdx.x) * 4;
    float4 v = *(const float4*)(x + i);
    unsigned lo = packh2(v.x, v.y);
    unsigned hi = packh2(v.z, v.w);
    *(uint2*)(xh + i) = make_uint2(lo, hi);
}

// ---------------------------------------------------------------------------
__global__ __launch_bounds__(256) void wtrans_kernel(
    const float* __restrict__ W, __half* __restrict__ WT, int R, int Cc)
{
    __shared__ unsigned short t[32][33];
    const int x = blockIdx.x * 32 + threadIdx.x;
    const int y0 = blockIdx.y * 32 + threadIdx.y;
#pragma unroll
    for (int i = 0; i < 4; ++i) {
        __half h = __float2half_rn(W[(size_t)(y0 + i * 8) * Cc + x]);
        t[threadIdx.y + i * 8][threadIdx.x] = *(unsigned short*)&h;
    }
    __syncthreads();
    const int xo = blockIdx.y * 32 + threadIdx.x;
    const int yo0 = blockIdx.x * 32 + threadIdx.y;
#pragma unroll
    for (int i = 0; i < 4; ++i) {
        unsigned short v = t[threadIdx.x][threadIdx.y + i * 8];
        WT[(size_t)(yo0 + i * 8) * R + xo] = *(__half*)&v;
    }
}

// ---------------------------------------------------------------------------
// FP16 mma.sync GEMM: C = A[M,K] * BT[N,K]^T, A/BT half.
// CTA tile 256x128, warp tile 64x64 (8 warps 4m x 2n), K-chunk = 64 halves,
// 3-stage cp.async pipeline, 16B-chunk rotation swizzle, m16n8k16.
// mode 0: fp32 row-major. mode 1: rope + half scatter (b,h,t,d).
// mode 2: half scatter (b,h,d,t).
// ---------------------------------------------------------------------------
__device__ __forceinline__ void gemmh_load_stage(
    uint32_t sb, int s, int kt,
    const __half* __restrict__ A, const __half* __restrict__ BT,
    int rowBase, int colBase, int K, int lr, int lcc, int chS)
{
    // stage = A 32KB + B 16KB = 48KB
    const uint32_t aBase = sb + (uint32_t)s * 49152u;
    const uint32_t bBase = aBase + 32768u;
#pragma unroll
    for (int c = 0; c < 8; ++c) {
        const int row = lr + c * 32;
        cp16(aBase + (uint32_t)(row * 128 + chS * 16),
             A + (size_t)(rowBase + row) * K + kt + lcc * 8);
    }
#pragma unroll
    for (int c = 0; c < 4; ++c) {
        const int row = lr + c * 32;
        cp16(bBase + (uint32_t)(row * 128 + chS * 16),
             BT + (size_t)(colBase + row) * K + kt + lcc * 8);
    }
    asm volatile("cp.async.commit_group;" ::: "memory");
}

__global__ __launch_bounds__(256) void fp16_gemm(
    const __half* __restrict__ A, const __half* __restrict__ BT,
    void* __restrict__ Cv, int N, int K, int mode, int HH)
{
    extern __shared__ unsigned smp[];   // 3 stages x 12288 words
    const uint32_t sb = smem_u32(smp);

    const int tid  = threadIdx.x;
    const int lane = tid & 31;
    const int w    = tid >> 5;
    const int wm   = (w >> 1) * 64;
    const int wn   = (w & 1) * 64;
    const int gr   = lane >> 2;
    const int gc   = lane & 3;

    const int rowBase = blockIdx.y * 256;
    const int colBase = blockIdx.x * 128;

    const int lr  = tid >> 3;            // 0..31
    const int lcc = tid & 7;             // 16B chunk 0..7
    const int chS = (lcc + (lr & 7)) & 7;

    float acc[4][8][4];
#pragma unroll
    for (int mi = 0; mi < 4; ++mi)
#pragma unroll
        for (int ni = 0; ni < 8; ++ni)
#pragma unroll
            for (int c = 0; c < 4; ++c) acc[mi][ni][c] = 0.f;

    const int nch = K / 64;
    gemmh_load_stage(sb, 0, 0,  A, BT, rowBase, colBase, K, lr, lcc, chS);
    gemmh_load_stage(sb, 1, 64, A, BT, rowBase, colBase, K, lr, lcc, chS);

    for (int ck = 0; ck < nch; ++ck) {
        const int s = ck % 3;
        if (ck + 2 < nch)
            asm volatile("cp.async.wait_group 1;" ::: "memory");
        else
            asm volatile("cp.async.wait_group 0;" ::: "memory");
        __syncthreads();
        if (ck + 2 < nch)
            gemmh_load_stage(sb, (ck + 2) % 3, (ck + 2) * 64,
                             A, BT, rowBase, colBase, K, lr, lcc, chS);

        const unsigned* As = smp + s * 12288;   // 256 rows x 32 words
        const unsigned* Bs = As + 8192;         // 128 rows x 32 words
#pragma unroll
        for (int kk = 0; kk < 64; kk += 16) {
            const int ch0 = kk >> 3;            // 0,2,4,6
            unsigned af[4][4], bf[8][2];
#pragma unroll
            for (int mi = 0; mi < 4; ++mi) {
                const int r = wm + mi * 16 + gr;
                const int sw0 = (((ch0    ) + gr) & 7) * 4 + gc;
                const int sw1 = (((ch0 + 1) + gr) & 7) * 4 + gc;
                af[mi][0] = As[r * 32 + sw0];
                af[mi][1] = As[(r + 8) * 32 + sw0];
                af[mi][2] = As[r * 32 + sw1];
                af[mi][3] = As[(r + 8) * 32 + sw1];
            }
#pragma unroll
            for (int ni = 0; ni < 8; ++ni) {
                const int rN = wn + ni * 8 + gr;
                const int sw0 = (((ch0    ) + gr) & 7) * 4 + gc;
                const int sw1 = (((ch0 + 1) + gr) & 7) * 4 + gc;
                bf[ni][0] = Bs[rN * 32 + sw0];
                bf[ni][1] = Bs[rN * 32 + sw1];
            }
#pragma unroll
            for (int mi = 0; mi < 4; ++mi)
#pragma unroll
                for (int ni = 0; ni < 8; ++ni) {
                    asm volatile(
                        "mma.sync.aligned.m16n8k16.row.col.f32.f16.f16.f32 "
                        "{%0,%1,%2,%3}, {%4,%5,%6,%7}, {%8,%9}, {%0,%1,%2,%3};"
                        : "+f"(acc[mi][ni][0]), "+f"(acc[mi][ni][1]),
                          "+f"(acc[mi][ni][2]), "+f"(acc[mi][ni][3])
                        : "r"(af[mi][0]), "r"(af[mi][1]),
                          "r"(af[mi][2]), "r"(af[mi][3]),
                          "r"(bf[ni][0]), "r"(bf[ni][1]));
                }
        }
    }

    // Epilogue
#pragma unroll
    for (int mi = 0; mi < 4; ++mi) {
#pragma unroll
        for (int ni = 0; ni < 8; ++ni) {
            const int row0 = rowBase + wm + mi * 16 + gr;
            const int col  = colBase + wn + ni * 8 + gc * 2;
            if (mode == 0) {
                float* C = (float*)Cv;
                *(float2*)(C + (size_t)row0 * N + col) =
                    make_float2(acc[mi][ni][0], acc[mi][ni][1]);
                *(float2*)(C + (size_t)(row0 + 8) * N + col) =
                    make_float2(acc[mi][ni][2], acc[mi][ni][3]);
            } else if (mode == 1) {  // rope + half scatter (b,h,t,d)
                __half* C = (__half*)Cv;
                const int h = col >> 7;
                const int d = col & (cD - 1);
                const int j = d >> 1;
                const float inv = exp2f(-13.287712379549449f * (float)j * (1.0f / 64.0f));
#pragma unroll
                for (int rr = 0; rr < 2; ++rr) {
                    const int row = row0 + rr * 8;
                    const int b = row >> 11;
                    const int t = row & (cT - 1);
                    float sn, cs;
                    sincosf((float)t * inv, &sn, &cs);
                    const float x0 = acc[mi][ni][rr*2];
                    const float x1 = acc[mi][ni][rr*2+1];
                    __half* p = C + ((size_t)(b * HH + h) * cT + t) * cD + d;
                    *(unsigned*)p = packh2(x0 * cs - x1 * sn, x0 * sn + x1 * cs);
                }
            } else {  // mode 2: half scatter (b,h,d,t)
                __half* C = (__half*)Cv;
                const int h = col >> 7;
                const int d = col & (cD - 1);
#pragma unroll
                for (int rr = 0; rr < 2; ++rr) {
                    const int row = row0 + rr * 8;
                    const int b = row >> 11;
                    const int t = row & (cT - 1);
                    __half* p = C + ((size_t)(b * HH + h) * cD + d) * cT + t;
                    p[0]  = __float2half_rn(acc[mi][ni][rr*2]);
                    p[cT] = __float2half_rn(acc[mi][ni][rr*2+1]);
                }
            }
        }
    }
}

// ---------------------------------------------------------------------------
// FP16 flash attention. Q/K/V half; m16n8k16; pads give stride==4 (mod 32).
// smem: Qs 128x68w + Ks 64x68w + Vs 128x36w + Ps 128x36w = 87.3 KB
// ---------------------------------------------------------------------------
__global__ __launch_bounds__(256) void attn_kernel(
    const __half* __restrict__ Q, const __half* __restrict__ K,
    const __half* __restrict__ VT, __half* __restrict__ AO)
{
    extern __shared__ unsigned sm[];
    unsigned* Qs = sm;                        // [128][68] words (136 halves)
    unsigned* Ks = Qs + 128 * 68;             // [64][68]
    unsigned* Vs = Ks + 64 * 68;              // [128][36] (72 halves; 64 used)
    unsigned* Ps = Vs + 128 * 36;             // [128][36]
    const uint32_t sQ = smem_u32(Qs);
    const uint32_t sK = smem_u32(Ks);
    const uint32_t sV = smem_u32(Vs);

    const int bid = blockIdx.x;
    const int qb  = bid & 15;
    const int h   = (bid >> 4) & 15;
    const int b   = bid >> 8;
    const int kvh = h >> 1;

    const __half* qptr  = Q  + ((size_t)(b * cH + h) * cT + qb * 128) * cD;
    const __half* kbase = K  + (size_t)(b * cKVH + kvh) * cT * cD;
    const __half* vbase = VT + (size_t)(b * cKVH + kvh) * cD * cT;

    const int tid  = threadIdx.x;
    const int lane = tid & 31;
    const int w    = tid >> 5;
    const int gr   = lane >> 2;
    const int gc   = lane & 3;
    const int wrow = w * 16;

    // Q fill: 128 rows x 16 chunks of 16B
#pragma unroll
    for (int it = 0; it < 8; ++it) {
        const int i = tid + it * 256;
        const int r = i >> 4, c16 = i & 15;
        cp16(sQ + (uint32_t)(r * 272 + c16 * 16), qptr + (size_t)r * cD + c16 * 8);
    }
    asm volatile("cp.async.commit_group;" ::: "memory");

    float m0 = -1e30f, m1 = -1e30f, l0 = 0.f, l1 = 0.f;
    float oacc[16][4];
#pragma unroll
    for (int ni = 0; ni < 16; ++ni)
#pragma unroll
        for (int c = 0; c < 4; ++c) oacc[ni][c] = 0.f;

    const float sc = 0.08838834764831845f * 1.4426950408889634f;
    const int qrow0 = qb * 128;
    const int nkv = 2 * qb + 2;

    for (int kt = 0; kt < nkv; ++kt) {
        __syncthreads();
        const __half* kp = kbase + (size_t)kt * 64 * cD;
        const __half* vp = vbase + kt * 64;
#pragma unroll
        for (int it = 0; it < 4; ++it) {
            const int i = tid + it * 256;
            {   // K: 64 rows x 16 chunks
                const int r = i >> 4, c16 = i & 15;
                cp16(sK + (uint32_t)(r * 272 + c16 * 16), kp + (size_t)r * cD + c16 * 8);
            }
            {   // V^T: 128 d-rows x 8 chunks (64 halves per row)
                const int d = i >> 3, c8 = i & 7;
                cp16(sV + (uint32_t)(d * 144 + c8 * 16), vp + (size_t)d * cT + c8 * 8);
            }
        }
        asm volatile("cp.async.commit_group;" ::: "memory");
        asm volatile("cp.async.wait_group 0;" ::: "memory");
        __syncthreads();

        // S = Q K^T : kk over 128 halves in steps of 16
        float s[8][4];
#pragma unroll
        for (int ni = 0; ni < 8; ++ni)
#pragma unroll
            for (int c = 0; c < 4; ++c) s[ni][c] = 0.f;

#pragma unroll
        for (int kk = 0; kk < 128; kk += 16) {
            const int wb = kk >> 1;
            unsigned a0 = Qs[(wrow + gr    ) * 68 + wb + gc    ];
            unsigned a1 = Qs[(wrow + gr + 8) * 68 + wb + gc    ];
            unsigned a2 = Qs[(wrow + gr    ) * 68 + wb + gc + 4];
            unsigned a3 = Qs[(wrow + gr + 8) * 68 + wb + gc + 4];
#pragma unroll
            for (int ni = 0; ni < 8; ++ni) {
                unsigned b0 = Ks[(ni * 8 + gr) * 68 + wb + gc    ];
                unsigned b1 = Ks[(ni * 8 + gr) * 68 + wb + gc + 4];
                asm volatile(
                    "mma.sync.aligned.m16n8k16.row.col.f32.f16.f16.f32 "
                    "{%0,%1,%2,%3}, {%4,%5,%6,%7}, {%8,%9}, {%0,%1,%2,%3};"
                    : "+f"(s[ni][0]), "+f"(s[ni][1]), "+f"(s[ni][2]), "+f"(s[ni][3])
                    : "r"(a0), "r"(a1), "r"(a2), "r"(a3), "r"(b0), "r"(b1));
            }
        }

        const bool diag = (kt >= 2 * qb);
        const int r0g = qrow0 + wrow + gr;
        const int r1g = r0g + 8;
#pragma unroll
        for (int ni = 0; ni < 8; ++ni) {
            const int col = kt * 64 + ni * 8 + gc * 2;
            s[ni][0] = (diag && col     > r0g) ? -1e30f : s[ni][0] * sc;
            s[ni][1] = (diag && col + 1 > r0g) ? -1e30f : s[ni][1] * sc;
            s[ni][2] = (diag && col     > r1g) ? -1e30f : s[ni][2] * sc;
            s[ni][3] = (diag && col + 1 > r1g) ? -1e30f : s[ni][3] * sc;
        }

        float mx0 = -1e30f, mx1 = -1e30f;
#pragma unroll
        for (int ni = 0; ni < 8; ++ni) {
            mx0 = fmaxf(mx0, fmaxf(s[ni][0], s[ni][1]));
            mx1 = fmaxf(mx1, fmaxf(s[ni][2], s[ni][3]));
        }
        mx0 = fmaxf(mx0, __shfl_xor_sync(0xffffffffu, mx0, 1));
        mx0 = fmaxf(mx0, __shfl_xor_sync(0xffffffffu, mx0, 2));
        mx1 = fmaxf(mx1, __shfl_xor_sync(0xffffffffu, mx1, 1));
        mx1 = fmaxf(mx1, __shfl_xor_sync(0xffffffffu, mx1, 2));

        const float mn0 = fmaxf(m0, mx0);
        const float mn1 = fmaxf(m1, mx1);
        const float cr0 = exp2f(m0 - mn0);
        const float cr1 = exp2f(m1 - mn1);
        m0 = mn0; m1 = mn1;

        float ls0 = 0.f, ls1 = 0.f;
#pragma unroll
        for (int ni = 0; ni < 8; ++ni) {
            float p0 = exp2f(s[ni][0] - mn0);
            float p1 = exp2f(s[ni][1] - mn0);
            float p2 = exp2f(s[ni][2] - mn1);
            float p3 = exp2f(s[ni][3] - mn1);
            ls0 += p0 + p1;
            ls1 += p2 + p3;
            Ps[(wrow + gr    ) * 36 + ni * 4 + gc] = packh2(p0, p1);
            Ps[(wrow + gr + 8) * 36 + ni * 4 + gc] = packh2(p2, p3);
        }
        ls0 += __shfl_xor_sync(0xffffffffu, ls0, 1);
        ls0 += __shfl_xor_sync(0xffffffffu, ls0, 2);
        ls1 += __shfl_xor_sync(0xffffffffu, ls1, 1);
        ls1 += __shfl_xor_sync(0xffffffffu, ls1, 2);
        l0 = l0 * cr0 + ls0;
        l1 = l1 * cr1 + ls1;

#pragma unroll
        for (int ni = 0; ni < 16; ++ni) {
            oacc[ni][0] *= cr0; oacc[ni][1] *= cr0;
            oacc[ni][2] *= cr1; oacc[ni][3] *= cr1;
        }
        __syncwarp();

        // O += P V : kk over 64 halves in steps of 16
#pragma unroll
        for (int kk = 0; kk < 64; kk += 16) {
            const int wb = kk >> 1;
            unsigned a0 = Ps[(wrow + gr    ) * 36 + wb + gc    ];
            unsigned a1 = Ps[(wrow + gr + 8) * 36 + wb + gc    ];
            unsigned a2 = Ps[(wrow + gr    ) * 36 + wb + gc + 4];
            unsigned a3 = Ps[(wrow + gr + 8) * 36 + wb + gc + 4];
#pragma unroll
            for (int ni = 0; ni < 16; ++ni) {
                unsigned b0 = Vs[(ni * 8 + gr) * 36 + wb + gc    ];
                unsigned b1 = Vs[(ni * 8 + gr) * 36 + wb + gc + 4];
                asm volatile(
                    "mma.sync.aligned.m16n8k16.row.col.f32.f16.f16.f32 "
                    "{%0,%1,%2,%3}, {%4,%5,%6,%7}, {%8,%9}, {%0,%1,%2,%3};"
                    : "+f"(oacc[ni][0]), "+f"(oacc[ni][1]),
                      "+f"(oacc[ni][2]), "+f"(oacc[ni][3])
                    : "r"(a0), "r"(a1), "r"(a2), "r"(a3), "r"(b0), "r"(b1));
            }
        }
    }

    const float i0 = 1.f / l0;
    const float i1 = 1.f / l1;
    const int t0 = qrow0 + wrow + gr;
#pragma unroll
    for (int ni = 0; ni < 16; ++ni) {
        const int d = ni * 8 + gc * 2;
        __half* p0 = AO + ((size_t)(b * cT + t0    ) * cH + h) * cD + d;
        __half* p1 = AO + ((size_t)(b * cT + t0 + 8) * cH + h) * cD + d;
        *(unsigned*)p0 = packh2(oacc[ni][0] * i0, oacc[ni][1] * i0);
        *(unsigned*)p1 = packh2(oacc[ni][2] * i1, oacc[ni][3] * i1);
    }
}

// ---------------------------------------------------------------------------
extern "C" void kernel_launch(void* const* d_in, const int* in_sizes, int n_in,
                              void* d_out, int out_size)
{
    const float* x  = (const float*)d_in[0];
    const float* wq = (const float*)d_in[2];
    const float* wk = (const float*)d_in[3];
    const float* wv = (const float*)d_in[4];
    const float* wo = (const float*)d_in[5];
    float* out = (float*)d_out;

    void *pq, *pk, *pv, *pao, *pxh, *pwq, *pwk, *pwv, *pwo;
    cudaGetSymbolAddress(&pq,  g_q);
    cudaGetSymbolAddress(&pk,  g_k);
    cudaGetSymbolAddress(&pv,  g_vt);
    cudaGetSymbolAddress(&pao, g_ao);
    cudaGetSymbolAddress(&pxh, g_xh);
    cudaGetSymbolAddress(&pwq, g_wqt);
    cudaGetSymbolAddress(&pwk, g_wkt);
    cudaGetSymbolAddress(&pwv, g_wvt);
    cudaGetSymbolAddress(&pwo, g_wot);
    __half* q   = (__half*)pq;
    __half* k   = (__half*)pk;
    __half* vt  = (__half*)pv;
    __half* ao  = (__half*)pao;
    __half* xh  = (__half*)pxh;
    __half* wqt = (__half*)pwq;
    __half* wkt = (__half*)pwk;
    __half* wvt = (__half*)pwv;
    __half* wot = (__half*)pwo;

    const int M = cB * cT;  // 4096

    quant_kernel<<<(int)(((size_t)M * cE / 4) / 256), 256>>>(x, xh);
    wtrans_kernel<<<dim3(2048 / 32, 2048 / 32), dim3(32, 8)>>>(wq, wqt, 2048, 2048);
    wtrans_kernel<<<dim3(1024 / 32, 2048 / 32), dim3(32, 8)>>>(wk, wkt, 2048, 1024);
    wtrans_kernel<<<dim3(1024 / 32, 2048 / 32), dim3(32, 8)>>>(wv, wvt, 2048, 1024);
    wtrans_kernel<<<dim3(2048 / 32, 2048 / 32), dim3(32, 8)>>>(wo, wot, 2048, 2048);

    const int gemm_smem = 3 * 49152;  // 147456
    cudaFuncSetAttribute(fp16_gemm, cudaFuncAttributeMaxDynamicSharedMemorySize, gemm_smem);

    // QKV projections (rope fused into q/k epilogues)
    fp16_gemm<<<dim3(16, 16), 256, gemm_smem>>>(xh, wqt, q,  cH * cD,   cE, 1, cH);
    fp16_gemm<<<dim3(8, 16),  256, gemm_smem>>>(xh, wkt, k,  cKVH * cD, cE, 1, cKVH);
    fp16_gemm<<<dim3(8, 16),  256, gemm_smem>>>(xh, wvt, vt, cKVH * cD, cE, 2, cKVH);

    const int attn_smem = (128 * 68 + 64 * 68 + 128 * 36 + 128 * 36) * 4;  // 89088
    cudaFuncSetAttribute(attn_kernel, cudaFuncAttributeMaxDynamicSharedMemorySize, attn_smem);
    attn_kernel<<<cB * cH * (cT / 128), 256, attn_smem>>>(q, k, vt, ao);

    // Output projection (fp32 row-major epilogue)
    fp16_gemm<<<dim3(16, 16), 256, gemm_smem>>>(ao, wot, out, cE, cE, 0, 0);
}

// round 13
// speedup vs baseline: 6.9062x; 1.1180x over previous
#include <cuda_runtime.h>
#include <cuda_fp16.h>
#include <math.h>
#include <cstdint>

constexpr int cB   = 2;
constexpr int cT   = 2048;
constexpr int cE   = 2048;
constexpr int cH   = 16;
constexpr int cKVH = 8;
constexpr int cD   = 128;

// Scratch (device globals). Half-precision operand buffers.
__device__ __half g_q   [(size_t)cB * cH   * cT * cD];   // (b,h,t,d) roped
__device__ __half g_k   [(size_t)cB * cKVH * cT * cD];   // (b,kvh,t,d) roped
__device__ __half g_vt  [(size_t)cB * cKVH * cD * cT];   // (b,kvh,d,t)
__device__ __half g_ao  [(size_t)cB * cT * cH * cD];     // (b,t,h,d)
__device__ __half g_xh  [(size_t)cB * cT * cE];          // x in half
// Concatenated transposed weights: rows [0,2048)=wq^T, [2048,3072)=wk^T, [3072,4096)=wv^T
__device__ __half g_wcat[(size_t)4096 * 2048];
__device__ __half g_wot [(size_t)2048 * 2048];

__device__ __forceinline__ uint32_t smem_u32(const void* p) {
    uint32_t a;
    asm("{ .reg .u64 t; cvta.to.shared.u64 t, %1; cvt.u32.u64 %0, t; }" : "=r"(a) : "l"(p));
    return a;
}

__device__ __forceinline__ void cp16(uint32_t dst, const void* src) {
    asm volatile("cp.async.cg.shared.global [%0], [%1], 16;"
                 :: "r"(dst), "l"(src) : "memory");
}

__device__ __forceinline__ unsigned packh2(float a, float b) {
    __half2 h = __floats2half2_rn(a, b);
    return *(unsigned*)&h;
}

// ---------------------------------------------------------------------------
__global__ __launch_bounds__(256) void quant_kernel(
    const float* __restrict__ x, __half* __restrict__ xh)
{
    const size_t i = ((size_t)blockIdx.x * 256 + threadIdx.x) * 4;
    float4 v = *(const float4*)(x + i);
    unsigned lo = packh2(v.x, v.y);
    unsigned hi = packh2(v.z, v.w);
    *(uint2*)(xh + i) = make_uint2(lo, hi);
}

// ---------------------------------------------------------------------------
__global__ __launch_bounds__(256) void wtrans_kernel(
    const float* __restrict__ W, __half* __restrict__ WT, int R, int Cc)
{
    __shared__ unsigned short t[32][33];
    const int x = blockIdx.x * 32 + threadIdx.x;
    const int y0 = blockIdx.y * 32 + threadIdx.y;
#pragma unroll
    for (int i = 0; i < 4; ++i) {
        __half h = __float2half_rn(W[(size_t)(y0 + i * 8) * Cc + x]);
        t[threadIdx.y + i * 8][threadIdx.x] = *(unsigned short*)&h;
    }
    __syncthreads();
    const int xo = blockIdx.y * 32 + threadIdx.x;
    const int yo0 = blockIdx.x * 32 + threadIdx.y;
#pragma unroll
    for (int i = 0; i < 4; ++i) {
        unsigned short v = t[threadIdx.x][threadIdx.y + i * 8];
        WT[(size_t)(yo0 + i * 8) * R + xo] = *(__half*)&v;
    }
}

// ---------------------------------------------------------------------------
// FP16 mma.sync GEMM v4: C = A[M,K] * BT[N,K]^T, A/BT half.
// CTA tile 128x128 (stage 32KB, 3-stage cp.async -> 96KB smem, 2 CTA/SM),
// warp tile 64x32 (8 warps 2m x 4n), K-chunk 64 halves, 16B rotation swizzle.
// mode 0: fp32 row-major out-proj.
// mode 3: fused QKV epilogue — segment by colBase: Q rope / K rope / V^T.
// ---------------------------------------------------------------------------
__device__ __forceinline__ void gemm4_load_stage(
    uint32_t sb, int s, int kt,
    const __half* __restrict__ A, const __half* __restrict__ BT,
    int rowBase, int colBase, int K, int lr, int lcc, int chS)
{
    // stage = A 16KB + B 16KB = 32KB
    const uint32_t aBase = sb + (uint32_t)s * 32768u;
    const uint32_t bBase = aBase + 16384u;
#pragma unroll
    for (int c = 0; c < 4; ++c) {
        const int row = lr + c * 32;
        cp16(aBase + (uint32_t)(row * 128 + chS * 16),
             A + (size_t)(rowBase + row) * K + kt + lcc * 8);
        cp16(bBase + (uint32_t)(row * 128 + chS * 16),
             BT + (size_t)(colBase + row) * K + kt + lcc * 8);
    }
    asm volatile("cp.async.commit_group;" ::: "memory");
}

__global__ __launch_bounds__(256) void fp16_gemm(
    const __half* __restrict__ A, const __half* __restrict__ BT,
    void* __restrict__ Cv,
    __half* __restrict__ Qo, __half* __restrict__ Ko, __half* __restrict__ Vo,
    int N, int K, int mode)
{
    extern __shared__ unsigned smp[];   // 3 stages x 8192 words
    const uint32_t sb = smem_u32(smp);

    const int tid  = threadIdx.x;
    const int lane = tid & 31;
    const int w    = tid >> 5;
    const int wm   = (w >> 2) * 64;     // 0,64
    const int wn   = (w & 3) * 32;      // 0,32,64,96
    const int gr   = lane >> 2;
    const int gc   = lane & 3;

    const int rowBase = blockIdx.y * 128;
    const int colBase = blockIdx.x * 128;

    const int lr  = tid >> 3;           // 0..31
    const int lcc = tid & 7;            // 16B chunk 0..7
    const int chS = (lcc + (lr & 7)) & 7;

    float acc[4][4][4];
#pragma unroll
    for (int mi = 0; mi < 4; ++mi)
#pragma unroll
        for (int ni = 0; ni < 4; ++ni)
#pragma unroll
            for (int c = 0; c < 4; ++c) acc[mi][ni][c] = 0.f;

    const int nch = K / 64;
    gemm4_load_stage(sb, 0, 0,  A, BT, rowBase, colBase, K, lr, lcc, chS);
    gemm4_load_stage(sb, 1, 64, A, BT, rowBase, colBase, K, lr, lcc, chS);

    for (int ck = 0; ck < nch; ++ck) {
        const int s = ck % 3;
        if (ck + 2 < nch)
            asm volatile("cp.async.wait_group 1;" ::: "memory");
        else
            asm volatile("cp.async.wait_group 0;" ::: "memory");
        __syncthreads();
        if (ck + 2 < nch)
            gemm4_load_stage(sb, (ck + 2) % 3, (ck + 2) * 64,
                             A, BT, rowBase, colBase, K, lr, lcc, chS);

        const unsigned* As = smp + s * 8192;    // 128 rows x 32 words
        const unsigned* Bs = As + 4096;         // 128 rows x 32 words
#pragma unroll
        for (int kk = 0; kk < 64; kk += 16) {
            const int ch0 = kk >> 3;            // 0,2,4,6
            const int sw0 = (((ch0    ) + gr) & 7) * 4 + gc;
            const int sw1 = (((ch0 + 1) + gr) & 7) * 4 + gc;
            unsigned af[4][4], bf[4][2];
#pragma unroll
            for (int mi = 0; mi < 4; ++mi) {
                const int r = wm + mi * 16 + gr;
                af[mi][0] = As[r * 32 + sw0];
                af[mi][1] = As[(r + 8) * 32 + sw0];
                af[mi][2] = As[r * 32 + sw1];
                af[mi][3] = As[(r + 8) * 32 + sw1];
            }
#pragma unroll
            for (int ni = 0; ni < 4; ++ni) {
                const int rN = wn + ni * 8 + gr;
                bf[ni][0] = Bs[rN * 32 + sw0];
                bf[ni][1] = Bs[rN * 32 + sw1];
            }
#pragma unroll
            for (int mi = 0; mi < 4; ++mi)
#pragma unroll
                for (int ni = 0; ni < 4; ++ni) {
                    asm volatile(
                        "mma.sync.aligned.m16n8k16.row.col.f32.f16.f16.f32 "
                        "{%0,%1,%2,%3}, {%4,%5,%6,%7}, {%8,%9}, {%0,%1,%2,%3};"
                        : "+f"(acc[mi][ni][0]), "+f"(acc[mi][ni][1]),
                          "+f"(acc[mi][ni][2]), "+f"(acc[mi][ni][3])
                        : "r"(af[mi][0]), "r"(af[mi][1]),
                          "r"(af[mi][2]), "r"(af[mi][3]),
                          "r"(bf[ni][0]), "r"(bf[ni][1]));
                }
        }
    }

    // ---- Epilogue ----
    if (mode == 0) {
        float* C = (float*)Cv;
#pragma unroll
        for (int mi = 0; mi < 4; ++mi)
#pragma unroll
            for (int ni = 0; ni < 4; ++ni) {
                const int row0 = rowBase + wm + mi * 16 + gr;
                const int col  = colBase + wn + ni * 8 + gc * 2;
                *(float2*)(C + (size_t)row0 * N + col) =
                    make_float2(acc[mi][ni][0], acc[mi][ni][1]);
                *(float2*)(C + (size_t)(row0 + 8) * N + col) =
                    make_float2(acc[mi][ni][2], acc[mi][ni][3]);
            }
        return;
    }

    // mode 3: fused QKV. Whole CTA lies in one segment (colBase multiple of 128).
    const int hcat = colBase >> 7;   // 0..15 Q-heads, 16..23 K-heads, 24..31 V-heads
    if (hcat < 24) {
        // Q or K: rope + scatter (b, h, t, d)
        __half* OutP = (hcat < 16) ? Qo : Ko;
        const int HH  = (hcat < 16) ? cH : cKVH;
        const int h   = (hcat < 16) ? hcat : hcat - 16;
#pragma unroll
        for (int mi = 0; mi < 4; ++mi)
#pragma unroll
            for (int ni = 0; ni < 4; ++ni) {
                const int row0 = rowBase + wm + mi * 16 + gr;
                const int col  = colBase + wn + ni * 8 + gc * 2;
                const int d = col & (cD - 1);
                const int j = d >> 1;
                const float inv = exp2f(-13.287712379549449f * (float)j * (1.0f / 64.0f));
#pragma unroll
                for (int rr = 0; rr < 2; ++rr) {
                    const int row = row0 + rr * 8;
                    const int b = row >> 11;
                    const int t = row & (cT - 1);
                    float sn, cs;
                    sincosf((float)t * inv, &sn, &cs);
                    const float x0 = acc[mi][ni][rr*2];
                    const float x1 = acc[mi][ni][rr*2+1];
                    __half* p = OutP + ((size_t)(b * HH + h) * cT + t) * cD + d;
                    *(unsigned*)p = packh2(x0 * cs - x1 * sn, x0 * sn + x1 * cs);
                }
            }
    } else {
        // V: scatter transposed (b, kvh, d, t)
        const int h = hcat - 24;
#pragma unroll
        for (int mi = 0; mi < 4; ++mi)
#pragma unroll
            for (int ni = 0; ni < 4; ++ni) {
                const int row0 = rowBase + wm + mi * 16 + gr;
                const int col  = colBase + wn + ni * 8 + gc * 2;
                const int d = col & (cD - 1);
#pragma unroll
                for (int rr = 0; rr < 2; ++rr) {
                    const int row = row0 + rr * 8;
                    const int b = row >> 11;
                    const int t = row & (cT - 1);
                    __half* p = Vo + ((size_t)(b * cKVH + h) * cD + d) * cT + t;
                    p[0]  = __float2half_rn(acc[mi][ni][rr*2]);
                    p[cT] = __float2half_rn(acc[mi][ni][rr*2+1]);
                }
            }
    }
}

// ---------------------------------------------------------------------------
// FP16 flash attention (unchanged from R12 — passing).
// ---------------------------------------------------------------------------
__global__ __launch_bounds__(256) void attn_kernel(
    const __half* __restrict__ Q, const __half* __restrict__ K,
    const __half* __restrict__ VT, __half* __restrict__ AO)
{
    extern __shared__ unsigned sm[];
    unsigned* Qs = sm;                        // [128][68] words
    unsigned* Ks = Qs + 128 * 68;             // [64][68]
    unsigned* Vs = Ks + 64 * 68;              // [128][36]
    unsigned* Ps = Vs + 128 * 36;             // [128][36]
    const uint32_t sQ = smem_u32(Qs);
    const uint32_t sK = smem_u32(Ks);
    const uint32_t sV = smem_u32(Vs);

    const int bid = blockIdx.x;
    const int qb  = bid & 15;
    const int h   = (bid >> 4) & 15;
    const int b   = bid >> 8;
    const int kvh = h >> 1;

    const __half* qptr  = Q  + ((size_t)(b * cH + h) * cT + qb * 128) * cD;
    const __half* kbase = K  + (size_t)(b * cKVH + kvh) * cT * cD;
    const __half* vbase = VT + (size_t)(b * cKVH + kvh) * cD * cT;

    const int tid  = threadIdx.x;
    const int lane = tid & 31;
    const int w    = tid >> 5;
    const int gr   = lane >> 2;
    const int gc   = lane & 3;
    const int wrow = w * 16;

#pragma unroll
    for (int it = 0; it < 8; ++it) {
        const int i = tid + it * 256;
        const int r = i >> 4, c16 = i & 15;
        cp16(sQ + (uint32_t)(r * 272 + c16 * 16), qptr + (size_t)r * cD + c16 * 8);
    }
    asm volatile("cp.async.commit_group;" ::: "memory");

    float m0 = -1e30f, m1 = -1e30f, l0 = 0.f, l1 = 0.f;
    float oacc[16][4];
#pragma unroll
    for (int ni = 0; ni < 16; ++ni)
#pragma unroll
        for (int c = 0; c < 4; ++c) oacc[ni][c] = 0.f;

    const float sc = 0.08838834764831845f * 1.4426950408889634f;
    const int qrow0 = qb * 128;
    const int nkv = 2 * qb + 2;

    for (int kt = 0; kt < nkv; ++kt) {
        __syncthreads();
        const __half* kp = kbase + (size_t)kt * 64 * cD;
        const __half* vp = vbase + kt * 64;
#pragma unroll
        for (int it = 0; it < 4; ++it) {
            const int i = tid + it * 256;
            {
                const int r = i >> 4, c16 = i & 15;
                cp16(sK + (uint32_t)(r * 272 + c16 * 16), kp + (size_t)r * cD + c16 * 8);
            }
            {
                const int d = i >> 3, c8 = i & 7;
                cp16(sV + (uint32_t)(d * 144 + c8 * 16), vp + (size_t)d * cT + c8 * 8);
            }
        }
        asm volatile("cp.async.commit_group;" ::: "memory");
        asm volatile("cp.async.wait_group 0;" ::: "memory");
        __syncthreads();

        float s[8][4];
#pragma unroll
        for (int ni = 0; ni < 8; ++ni)
#pragma unroll
            for (int c = 0; c < 4; ++c) s[ni][c] = 0.f;

#pragma unroll
        for (int kk = 0; kk < 128; kk += 16) {
            const int wb = kk >> 1;
            unsigned a0 = Qs[(wrow + gr    ) * 68 + wb + gc    ];
            unsigned a1 = Qs[(wrow + gr + 8) * 68 + wb + gc    ];
            unsigned a2 = Qs[(wrow + gr    ) * 68 + wb + gc + 4];
            unsigned a3 = Qs[(wrow + gr + 8) * 68 + wb + gc + 4];
#pragma unroll
            for (int ni = 0; ni < 8; ++ni) {
                unsigned b0 = Ks[(ni * 8 + gr) * 68 + wb + gc    ];
                unsigned b1 = Ks[(ni * 8 + gr) * 68 + wb + gc + 4];
                asm volatile(
                    "mma.sync.aligned.m16n8k16.row.col.f32.f16.f16.f32 "
                    "{%0,%1,%2,%3}, {%4,%5,%6,%7}, {%8,%9}, {%0,%1,%2,%3};"
                    : "+f"(s[ni][0]), "+f"(s[ni][1]), "+f"(s[ni][2]), "+f"(s[ni][3])
                    : "r"(a0), "r"(a1), "r"(a2), "r"(a3), "r"(b0), "r"(b1));
            }
        }

        const bool diag = (kt >= 2 * qb);
        const int r0g = qrow0 + wrow + gr;
        const int r1g = r0g + 8;
#pragma unroll
        for (int ni = 0; ni < 8; ++ni) {
            const int col = kt * 64 + ni * 8 + gc * 2;
            s[ni][0] = (diag && col     > r0g) ? -1e30f : s[ni][0] * sc;
            s[ni][1] = (diag && col + 1 > r0g) ? -1e30f : s[ni][1] * sc;
            s[ni][2] = (diag && col     > r1g) ? -1e30f : s[ni][2] * sc;
            s[ni][3] = (diag && col + 1 > r1g) ? -1e30f : s[ni][3] * sc;
        }

        float mx0 = -1e30f, mx1 = -1e30f;
#pragma unroll
        for (int ni = 0; ni < 8; ++ni) {
            mx0 = fmaxf(mx0, fmaxf(s[ni][0], s[ni][1]));
            mx1 = fmaxf(mx1, fmaxf(s[ni][2], s[ni][3]));
        }
        mx0 = fmaxf(mx0, __shfl_xor_sync(0xffffffffu, mx0, 1));
        mx0 = fmaxf(mx0, __shfl_xor_sync(0xffffffffu, mx0, 2));
        mx1 = fmaxf(mx1, __shfl_xor_sync(0xffffffffu, mx1, 1));
        mx1 = fmaxf(mx1, __shfl_xor_sync(0xffffffffu, mx1, 2));

        const float mn0 = fmaxf(m0, mx0);
        const float mn1 = fmaxf(m1, mx1);
        const float cr0 = exp2f(m0 - mn0);
        const float cr1 = exp2f(m1 - mn1);
        m0 = mn0; m1 = mn1;

        float ls0 = 0.f, ls1 = 0.f;
#pragma unroll
        for (int ni = 0; ni < 8; ++ni) {
            float p0 = exp2f(s[ni][0] - mn0);
            float p1 = exp2f(s[ni][1] - mn0);
            float p2 = exp2f(s[ni][2] - mn1);
            float p3 = exp2f(s[ni][3] - mn1);
            ls0 += p0 + p1;
            ls1 += p2 + p3;
            Ps[(wrow + gr    ) * 36 + ni * 4 + gc] = packh2(p0, p1);
            Ps[(wrow + gr + 8) * 36 + ni * 4 + gc] = packh2(p2, p3);
        }
        ls0 += __shfl_xor_sync(0xffffffffu, ls0, 1);
        ls0 += __shfl_xor_sync(0xffffffffu, ls0, 2);
        ls1 += __shfl_xor_sync(0xffffffffu, ls1, 1);
        ls1 += __shfl_xor_sync(0xffffffffu, ls1, 2);
        l0 = l0 * cr0 + ls0;
        l1 = l1 * cr1 + ls1;

#pragma unroll
        for (int ni = 0; ni < 16; ++ni) {
            oacc[ni][0] *= cr0; oacc[ni][1] *= cr0;
            oacc[ni][2] *= cr1; oacc[ni][3] *= cr1;
        }
        __syncwarp();

#pragma unroll
        for (int kk = 0; kk < 64; kk += 16) {
            const int wb = kk >> 1;
            unsigned a0 = Ps[(wrow + gr    ) * 36 + wb + gc    ];
            unsigned a1 = Ps[(wrow + gr + 8) * 36 + wb + gc    ];
            unsigned a2 = Ps[(wrow + gr    ) * 36 + wb + gc + 4];
            unsigned a3 = Ps[(wrow + gr + 8) * 36 + wb + gc + 4];
#pragma unroll
            for (int ni = 0; ni < 16; ++ni) {
                unsigned b0 = Vs[(ni * 8 + gr) * 36 + wb + gc    ];
                unsigned b1 = Vs[(ni * 8 + gr) * 36 + wb + gc + 4];
                asm volatile(
                    "mma.sync.aligned.m16n8k16.row.col.f32.f16.f16.f32 "
                    "{%0,%1,%2,%3}, {%4,%5,%6,%7}, {%8,%9}, {%0,%1,%2,%3};"
                    : "+f"(oacc[ni][0]), "+f"(oacc[ni][1]),
                      "+f"(oacc[ni][2]), "+f"(oacc[ni][3])
                    : "r"(a0), "r"(a1), "r"(a2), "r"(a3), "r"(b0), "r"(b1));
            }
        }
    }

    const float i0 = 1.f / l0;
    const float i1 = 1.f / l1;
    const int t0 = qrow0 + wrow + gr;
#pragma unroll
    for (int ni = 0; ni < 16; ++ni) {
        const int d = ni * 8 + gc * 2;
        __half* p0 = AO + ((size_t)(b * cT + t0    ) * cH + h) * cD + d;
        __half* p1 = AO + ((size_t)(b * cT + t0 + 8) * cH + h) * cD + d;
        *(unsigned*)p0 = packh2(oacc[ni][0] * i0, oacc[ni][1] * i0);
        *(unsigned*)p1 = packh2(oacc[ni][2] * i1, oacc[ni][3] * i1);
    }
}

// ---------------------------------------------------------------------------
extern "C" void kernel_launch(void* const* d_in, const int* in_sizes, int n_in,
                              void* d_out, int out_size)
{
    const float* x  = (const float*)d_in[0];
    const float* wq = (const float*)d_in[2];
    const float* wk = (const float*)d_in[3];
    const float* wv = (const float*)d_in[4];
    const float* wo = (const float*)d_in[5];
    float* out = (float*)d_out;

    void *pq, *pk, *pv, *pao, *pxh, *pwc, *pwo;
    cudaGetSymbolAddress(&pq,  g_q);
    cudaGetSymbolAddress(&pk,  g_k);
    cudaGetSymbolAddress(&pv,  g_vt);
    cudaGetSymbolAddress(&pao, g_ao);
    cudaGetSymbolAddress(&pxh, g_xh);
    cudaGetSymbolAddress(&pwc, g_wcat);
    cudaGetSymbolAddress(&pwo, g_wot);
    __half* q    = (__half*)pq;
    __half* k    = (__half*)pk;
    __half* vt   = (__half*)pv;
    __half* ao   = (__half*)pao;
    __half* xh   = (__half*)pxh;
    __half* wcat = (__half*)pwc;
    __half* wot  = (__half*)pwo;

    const int M = cB * cT;  // 4096

    quant_kernel<<<(int)(((size_t)M * cE / 4) / 256), 256>>>(x, xh);
    // Transposes into the concatenated buffer (row offsets 0 / 2048 / 3072)
    wtrans_kernel<<<dim3(2048 / 32, 2048 / 32), dim3(32, 8)>>>(wq, wcat, 2048, 2048);
    wtrans_kernel<<<dim3(1024 / 32, 2048 / 32), dim3(32, 8)>>>(wk, wcat + (size_t)2048 * 2048, 2048, 1024);
    wtrans_kernel<<<dim3(1024 / 32, 2048 / 32), dim3(32, 8)>>>(wv, wcat + (size_t)3072 * 2048, 2048, 1024);
    wtrans_kernel<<<dim3(2048 / 32, 2048 / 32), dim3(32, 8)>>>(wo, wot, 2048, 2048);

    const int gemm_smem = 3 * 32768;  // 98304 -> 2 CTAs/SM
    cudaFuncSetAttribute(fp16_gemm, cudaFuncAttributeMaxDynamicSharedMemorySize, gemm_smem);

    // Fused QKV projection: one launch, 32x32 = 1024 CTAs
    fp16_gemm<<<dim3(32, 32), 256, gemm_smem>>>(xh, wcat, nullptr, q, k, vt, 4096, cE, 3);

    const int attn_smem = (128 * 68 + 64 * 68 + 128 * 36 + 128 * 36) * 4;  // 89088
    cudaFuncSetAttribute(attn_kernel, cudaFuncAttributeMaxDynamicSharedMemorySize, attn_smem);
    attn_kernel<<<cB * cH * (cT / 128), 256, attn_smem>>>(q, k, vt, ao);

    // Output projection (fp32 row-major epilogue)
    fp16_gemm<<<dim3(16, 32), 256, gemm_smem>>>(ao, wot, out, nullptr, nullptr, nullptr, cE, cE, 0);
}